// round 13
// baseline (speedup 1.0000x reference)
#include <cuda_runtime.h>
#include <cuda_fp16.h>
#include <cstdint>

// Problem constants
static constexpr int Bc  = 2;
static constexpr int Lc  = 2048;
static constexpr int Dc  = 1024;
static constexpr int Hc  = 16;

// Scratch (__device__ globals: allocation-free rule)
__device__ __half g_qk  [(size_t)Bc * Lc * 2 * Dc];     // [4096][2048] q|k fp16
__device__ __half g_S   [(size_t)Bc * Lc * Hc * Lc];    // exp(score-6) fp16, [b][q][h][k]
__device__ __half g_xh  [(size_t)Bc * Lc * Dc];         // x fp16
__device__ __half g_Wh  [(size_t)2 * Dc * Dc];          // W[:2048] fp16
__device__ __half g_xTh [(size_t)Bc * Dc * Lc];         // x^T fp16
__device__ __half g_atnH[(size_t)Bc * Lc * Lc];         // attn fp16 (K5 operand)
__device__ float  g_part[(size_t)Bc * Hc * 16 * Lc];    // per-ntile row sums
__device__ float  g_attn[(size_t)Bc * Lc * Lc];         // fallback attn buffer

// ---------------------------------------------------------------------------
__device__ __forceinline__ uint32_t smem_u32(const void* p) {
    uint32_t a;
    asm("{ .reg .u64 t; cvta.to.shared.u64 t, %1; cvt.u32.u64 %0, t; }" : "=r"(a) : "l"(p));
    return a;
}
__device__ __forceinline__ void mma16(float* c, const uint32_t* a, const uint32_t* b) {
    asm volatile(
        "mma.sync.aligned.m16n8k16.row.col.f32.f16.f16.f32 "
        "{%0,%1,%2,%3}, {%4,%5,%6,%7}, {%8,%9}, {%0,%1,%2,%3};"
        : "+f"(c[0]), "+f"(c[1]), "+f"(c[2]), "+f"(c[3])
        : "r"(a[0]), "r"(a[1]), "r"(a[2]), "r"(a[3]), "r"(b[0]), "r"(b[1]));
}
#define LDMX4(r0, r1, r2, r3, addr) \
    asm volatile("ldmatrix.sync.aligned.m8n8.x4.shared.b16 {%0,%1,%2,%3}, [%4];" \
        : "=r"(r0), "=r"(r1), "=r"(r2), "=r"(r3) : "r"(addr))
__device__ __forceinline__ void cp_async16(uint32_t dst, const void* src) {
    asm volatile("cp.async.cg.shared.global [%0], [%1], 16;" :: "r"(dst), "l"(src));
}
#define CP_COMMIT() asm volatile("cp.async.commit_group;" ::: "memory")
#define CP_WAIT(N)  asm volatile("cp.async.wait_group %0;" :: "n"(N) : "memory")

static constexpr int CHUNK = 64;
static constexpr int PADH  = 72;                        // 64 + 8 pad halves
static constexpr int AB_HALVES = 128 * PADH;            // 9216
static constexpr int STAGE_HALVES = 2 * AB_HALVES;      // A then B
static constexpr int NSTAGE = 3;
static constexpr int SMEM_GEMM_BYTES = NSTAGE * STAGE_HALVES * 2;   // 110592

// ---------------------------------------------------------------------------
// fp16 warp-MMA GEMM (K1/K5): C = f(alpha * A @ B^T)
// EPI: 0 = fp32 store (streaming), 1 = +bias -> fp16
// 512 thr = 16 warps (4m x 4n), warp tile 32x32, k-chunk 64, 3-stage ring,
// launch_bounds(512,2) -> 1024 threads/SM.
// ---------------------------------------------------------------------------
template <int EPI, typename CT>
__global__ __launch_bounds__(512, 2)
void gemm_h(const __half* __restrict__ A, int lda, long aOut, long aIn,
            const __half* __restrict__ B, int ldb, long bOut, long bIn,
            CT* __restrict__ C, int ldc, long cOut, long cIn,
            int zInner, int Kd, float alpha, const float* __restrict__ bias)
{
    extern __shared__ __align__(16) char smemc[];
    const uint32_t sb = smem_u32(smemc);

    const int tid  = threadIdx.x;
    const int wid  = tid >> 5;          // 0..15
    const int lane = tid & 31;
    const int wm   = wid >> 2;          // 0..3
    const int wn   = wid & 3;           // 0..3
    const int lq   = lane >> 2;         // 0..7
    const int lr   = lane & 3;          // 0..3

    const int z  = blockIdx.z;
    const int zo = z / zInner, zi = z % zInner;
    A += (long)zo * aOut + (long)zi * aIn;
    B += (long)zo * bOut + (long)zi * bIn;
    C += (long)zo * cOut + (long)zi * cIn;

    const int m0 = blockIdx.y * 128;
    const int n0 = blockIdx.x * 128;

    float acc[2][4][4];
#pragma unroll
    for (int mt = 0; mt < 2; mt++)
#pragma unroll
        for (int nt = 0; nt < 4; nt++)
#pragma unroll
            for (int i = 0; i < 4; i++) acc[mt][nt][i] = 0.0f;

    const int nc = Kd / CHUNK;

    auto preload = [&](int c, int s) {
        const int k0 = c * CHUNK;
        const uint32_t abase = sb + (uint32_t)(s * STAGE_HALVES) * 2;
        const uint32_t bbase = abase + (uint32_t)AB_HALVES * 2;
#pragma unroll
        for (int j = 0; j < 2; j++) {
            const int f   = j * 512 + tid;
            const int row = f >> 3;
            const int c8  = f & 7;
            const uint32_t off = (uint32_t)(row * PADH + c8 * 8) * 2;
            cp_async16(abase + off, &A[(size_t)(m0 + row) * lda + k0 + c8 * 8]);
            cp_async16(bbase + off, &B[(size_t)(n0 + row) * ldb + k0 + c8 * 8]);
        }
    };

    preload(0, 0);
    CP_COMMIT();
    if (nc > 1) { preload(1, 1); CP_COMMIT(); }

    int s = 0;
    for (int c = 0; c < nc; c++) {
        if (c + 1 < nc) { CP_WAIT(1); } else { CP_WAIT(0); }
        __syncthreads();
        if (c + 2 < nc) {
            int s2 = s + 2; if (s2 >= NSTAGE) s2 -= NSTAGE;
            preload(c + 2, s2);
            CP_COMMIT();
        }

        const uint32_t stA = sb + (uint32_t)(s * STAGE_HALVES) * 2;
        const uint32_t stB = stA + (uint32_t)AB_HALVES * 2;

#pragma unroll
        for (int kh = 0; kh < CHUNK / 16; kh++) {
            uint32_t af[2][4];
#pragma unroll
            for (int mt = 0; mt < 2; mt++) {
                const int row = wm * 32 + mt * 16 + (lane & 7) + ((lane >> 3) & 1) * 8;
                const int col = kh * 16 + (lane >> 4) * 8;
                LDMX4(af[mt][0], af[mt][1], af[mt][2], af[mt][3],
                      stA + (uint32_t)(row * PADH + col) * 2);
            }
#pragma unroll
            for (int np = 0; np < 2; np++) {
                const int rowb = wn * 32 + np * 16 + (lane >> 4) * 8 + (lane & 7);
                const int colk = kh * 16 + ((lane >> 3) & 1) * 8;
                uint32_t bf[4];
                LDMX4(bf[0], bf[1], bf[2], bf[3],
                      stB + (uint32_t)(rowb * PADH + colk) * 2);
                mma16(acc[0][np * 2    ], af[0], bf + 0);
                mma16(acc[1][np * 2    ], af[1], bf + 0);
                mma16(acc[0][np * 2 + 1], af[0], bf + 2);
                mma16(acc[1][np * 2 + 1], af[1], bf + 2);
            }
        }
        if (++s >= NSTAGE) s -= NSTAGE;
    }
    __syncthreads();

    // ---- epilogue: regs -> fp32 staged smem -> coalesced GMEM ----
    float* stg = (float*)smemc;                        // 128 x 132 floats (67.6KB)
#pragma unroll
    for (int mt = 0; mt < 2; mt++) {
        const int r = wm * 32 + mt * 16 + lq;
#pragma unroll
        for (int nt = 0; nt < 4; nt++) {
            const int cI = wn * 32 + nt * 8 + 2 * lr;
            *(float2*)&stg[(r    ) * 132 + cI] =
                make_float2(acc[mt][nt][0] * alpha, acc[mt][nt][1] * alpha);
            *(float2*)&stg[(r + 8) * 132 + cI] =
                make_float2(acc[mt][nt][2] * alpha, acc[mt][nt][3] * alpha);
        }
    }
    __syncthreads();

    float4 bv = make_float4(0.f, 0.f, 0.f, 0.f);
    if (EPI == 1) bv = *(const float4*)&bias[n0 + lane * 4];
#pragma unroll
    for (int it = 0; it < 8; it++) {
        const int r2 = it * 16 + wid;
        float4 v = *(const float4*)&stg[r2 * 132 + lane * 4];
        if (EPI == 1) { v.x += bv.x; v.y += bv.y; v.z += bv.z; v.w += bv.w; }
        if (EPI == 0) {
            // final output: never re-read -> streaming store
            __stcs((float4*)&C[(size_t)(m0 + r2) * ldc + n0 + lane * 4], v);
        } else {
            __half2 h0 = __floats2half2_rn(v.x, v.y);
            __half2 h1 = __floats2half2_rn(v.z, v.w);
            uint2 u;
            u.x = *(uint32_t*)&h0; u.y = *(uint32_t*)&h1;
            *(uint2*)&C[(size_t)(m0 + r2) * ldc + n0 + lane * 4] = u;
        }
    }
}

// ---------------------------------------------------------------------------
// K2: dedicated scores kernel. 512 thr = 16 warps (4m x 4n), warp tile 32x32,
// single K=64 chunk, exp(0.125*acc-6) epilogue, fp16 staging, interleaved S
// layout [b][q][h][k], per-row partial sums. launch_bounds(512,2) -> 2 CTA/SM.
// S stores use __stcs (evict-first): keeps qk resident in L2 across K2.
// ---------------------------------------------------------------------------
static constexpr int PADS = 136;                        // staging halves/row
static constexpr int SMEM_K2_BYTES = STAGE_HALVES * 2;  // 36864 (one stage)
// staging needs 128*136*2 = 34816 <= 36864  OK

__global__ __launch_bounds__(512, 2)
void gemm_exp_kernel(const __half* __restrict__ qk, __half* __restrict__ S,
                     float* __restrict__ partial)
{
    extern __shared__ __align__(16) char smemc[];
    const uint32_t sb = smem_u32(smemc);

    const int tid  = threadIdx.x;
    const int wid  = tid >> 5;          // 0..15
    const int lane = tid & 31;
    const int wm   = wid >> 2;          // 0..3
    const int wn   = wid & 3;           // 0..3
    const int lq   = lane >> 2;         // 0..7
    const int lr   = lane & 3;          // 0..3

    const int z = blockIdx.z;           // b*16 + h
    const int b = z >> 4, h = z & 15;
    const int m0 = blockIdx.y * 128;    // q base
    const int n0 = blockIdx.x * 128;    // k base

    const __half* A = qk + (size_t)b * Lc * 2 * Dc + (size_t)h * 64;   // q
    const __half* B = A + Dc;                                          // k
    const int ld = 2 * Dc;

    // load 128x64 A and B tiles (one stage)
    {
        const uint32_t abase = sb;
        const uint32_t bbase = sb + (uint32_t)AB_HALVES * 2;
#pragma unroll
        for (int j = 0; j < 2; j++) {
            const int f   = j * 512 + tid;
            const int row = f >> 3;
            const int c8  = f & 7;
            const uint32_t off = (uint32_t)(row * PADH + c8 * 8) * 2;
            cp_async16(abase + off, &A[(size_t)(m0 + row) * ld + c8 * 8]);
            cp_async16(bbase + off, &B[(size_t)(n0 + row) * ld + c8 * 8]);
        }
    }
    CP_COMMIT();
    CP_WAIT(0);
    __syncthreads();

    float acc[2][4][4];
#pragma unroll
    for (int mt = 0; mt < 2; mt++)
#pragma unroll
        for (int nt = 0; nt < 4; nt++)
#pragma unroll
            for (int i = 0; i < 4; i++) acc[mt][nt][i] = 0.0f;

    const uint32_t stA = sb;
    const uint32_t stB = sb + (uint32_t)AB_HALVES * 2;

#pragma unroll
    for (int kh = 0; kh < 4; kh++) {
        uint32_t af[2][4];
#pragma unroll
        for (int mt = 0; mt < 2; mt++) {
            const int row = wm * 32 + mt * 16 + (lane & 7) + ((lane >> 3) & 1) * 8;
            const int col = kh * 16 + (lane >> 4) * 8;
            LDMX4(af[mt][0], af[mt][1], af[mt][2], af[mt][3],
                  stA + (uint32_t)(row * PADH + col) * 2);
        }
#pragma unroll
        for (int np = 0; np < 2; np++) {
            const int rowb = wn * 32 + np * 16 + (lane >> 4) * 8 + (lane & 7);
            const int colk = kh * 16 + ((lane >> 3) & 1) * 8;
            uint32_t bf[4];
            LDMX4(bf[0], bf[1], bf[2], bf[3],
                  stB + (uint32_t)(rowb * PADH + colk) * 2);
            mma16(acc[0][np * 2    ], af[0], bf + 0);
            mma16(acc[1][np * 2    ], af[1], bf + 0);
            mma16(acc[0][np * 2 + 1], af[0], bf + 2);
            mma16(acc[1][np * 2 + 1], af[1], bf + 2);
        }
    }
    __syncthreads();            // operand smem about to be reused as staging

    // exp + fp16 staging
    __half* stgh = (__half*)smemc;      // 128 x PADS halves
#pragma unroll
    for (int mt = 0; mt < 2; mt++) {
        const int r = wm * 32 + mt * 16 + lq;
#pragma unroll
        for (int nt = 0; nt < 4; nt++) {
            const int cI = wn * 32 + nt * 8 + 2 * lr;
            float v0 = __expf(0.125f * acc[mt][nt][0] - 6.0f);
            float v1 = __expf(0.125f * acc[mt][nt][1] - 6.0f);
            float v2 = __expf(0.125f * acc[mt][nt][2] - 6.0f);
            float v3 = __expf(0.125f * acc[mt][nt][3] - 6.0f);
            *(__half2*)&stgh[(r    ) * PADS + cI] = __floats2half2_rn(v0, v1);
            *(__half2*)&stgh[(r + 8) * PADS + cI] = __floats2half2_rn(v2, v3);
        }
    }
    __syncthreads();

    // per-row partial sums (4 threads/row, 32 halves each, shfl-reduce)
    {
        const int row = tid >> 2;
        const int q4  = tid & 3;
        float sum = 0.0f;
#pragma unroll
        for (int j = 0; j < 4; j++) {
            const uint4 u = *(const uint4*)&stgh[row * PADS + q4 * 32 + j * 8];
            float2 f0 = __half22float2(*(const __half2*)&u.x);
            float2 f1 = __half22float2(*(const __half2*)&u.y);
            float2 f2 = __half22float2(*(const __half2*)&u.z);
            float2 f3 = __half22float2(*(const __half2*)&u.w);
            sum += f0.x + f0.y + f1.x + f1.y + f2.x + f2.y + f3.x + f3.y;
        }
        sum += __shfl_xor_sync(0xFFFFFFFFu, sum, 1);
        sum += __shfl_xor_sync(0xFFFFFFFFu, sum, 2);
        if (q4 == 0)
            partial[(size_t)(z * 16 + blockIdx.x) * Lc + m0 + row] = sum;
    }

    // store S (streaming, evict-first): [b][q][h][k]; 2048 uint4 slots
#pragma unroll
    for (int it = 0; it < 4; it++) {
        const int slot = tid + it * 512;
        const int row  = slot >> 4;
        const int c16  = slot & 15;
        const uint4 u = *(const uint4*)&stgh[row * PADS + c16 * 8];
        __stcs((uint4*)&S[(((size_t)b * Lc + m0 + row) * Hc + h) * Lc + n0 + c16 * 8], u);
    }
}

// ---------------------------------------------------------------------------
// Combined prep kernel (one launch):
//   blocks [0,2048)      : x  fp32 -> xh fp16       (8 elems/thread)
//   blocks [2048,3072)   : W  fp32 -> Wh fp16
//   blocks [3072,7168)   : x  -> xTh transpose fp16 (32x32 tiles)
// ---------------------------------------------------------------------------
__global__ __launch_bounds__(256)
void prep_kernel(const float* __restrict__ x, const float* __restrict__ W,
                 __half* __restrict__ xh, __half* __restrict__ Wh,
                 __half* __restrict__ xTh)
{
    const int bid = blockIdx.x;
    const int tid = threadIdx.x;

    if (bid < 3072) {
        const float* src = (bid < 2048) ? x : W;
        __half* dst      = (bid < 2048) ? xh : Wh;
        const size_t base = (size_t)(bid < 2048 ? bid : bid - 2048) * 2048;
        const size_t i = base + (size_t)tid * 8;
        float4 a = *(const float4*)&src[i];
        float4 b = *(const float4*)&src[i + 4];
        __half2 h0 = __floats2half2_rn(a.x, a.y);
        __half2 h1 = __floats2half2_rn(a.z, a.w);
        __half2 h2 = __floats2half2_rn(b.x, b.y);
        __half2 h3 = __floats2half2_rn(b.z, b.w);
        uint4 u;
        u.x = *(uint32_t*)&h0; u.y = *(uint32_t*)&h1;
        u.z = *(uint32_t*)&h2; u.w = *(uint32_t*)&h3;
        *(uint4*)&dst[i] = u;
        return;
    }

    __shared__ float t[32][33];
    const int r  = bid - 3072;
    const int b  = r >> 11;
    const int rr = r & 2047;
    const int l0 = (rr >> 5) * 32;
    const int d0 = (rr & 31) * 32;
    const int tx = tid & 31;
    const int ty = tid >> 5;
#pragma unroll
    for (int j = 0; j < 4; j++)
        t[ty + 8 * j][tx] = x[(size_t)b * Lc * Dc + (size_t)(l0 + ty + 8 * j) * Dc + d0 + tx];
    __syncthreads();
#pragma unroll
    for (int j = 0; j < 4; j++)
        xTh[(size_t)b * Dc * Lc + (size_t)(d0 + ty + 8 * j) * Lc + l0 + tx] =
            __float2half_rn(t[tx][ty + 8 * j]);
}

// ---------------------------------------------------------------------------
// K4': gs-fold + head-mean of exp-scores + decay + renormalize.
// S layout [b][q][h][k] -> contiguous 64KB per (b,q), streamed via __ldcs.
// td streamed via __ldcs; fp32 attn out via __stcs; attnH normal (K5 re-reads).
// ---------------------------------------------------------------------------
__global__ __launch_bounds__(256)
void attn_kernel(const __half* __restrict__ E, const float* __restrict__ part,
                 const float* __restrict__ td, float* __restrict__ attn,
                 __half* __restrict__ attnH)
{
    const int bq = blockIdx.x;
    const int b  = bq >> 11;
    const int q  = bq & (Lc - 1);
    const int tid = threadIdx.x;

    __shared__ float red2[256];
    __shared__ float ish[Hc];
    __shared__ float red[8];

    {
        const int h = tid >> 4, kt = tid & 15;
        red2[tid] = part[((size_t)((b * Hc + h) * 16 + kt)) * Lc + q];
    }
    __syncthreads();
    if (tid < Hc) {
        float s = 0.0f;
#pragma unroll
        for (int kt = 0; kt < 16; kt++) s += red2[tid * 16 + kt];
        ish[tid] = 1.0f / (16.0f * s);
    }
    __syncthreads();

    const __half* Eq = E + (size_t)bq * Hc * Lc;

    // hoist td loads (streamed once)
    const float4 t0 = __ldcs((const float4*)&td[(size_t)bq * Lc + 8 * tid]);
    const float4 t1 = __ldcs((const float4*)&td[(size_t)bq * Lc + 8 * tid + 4]);

    float acc[8];
#pragma unroll
    for (int j = 0; j < 8; j++) acc[j] = 0.0f;

#pragma unroll
    for (int hb = 0; hb < Hc; hb += 4) {
        uint4 u[4];
#pragma unroll
        for (int i = 0; i < 4; i++)
            u[i] = __ldcs((const uint4*)&Eq[(size_t)(hb + i) * Lc + 8 * tid]);
#pragma unroll
        for (int i = 0; i < 4; i++) {
            const float is = ish[hb + i];
            float2 f0 = __half22float2(*(const __half2*)&u[i].x);
            float2 f1 = __half22float2(*(const __half2*)&u[i].y);
            float2 f2 = __half22float2(*(const __half2*)&u[i].z);
            float2 f3 = __half22float2(*(const __half2*)&u[i].w);
            acc[0] += f0.x * is; acc[1] += f0.y * is;
            acc[2] += f1.x * is; acc[3] += f1.y * is;
            acc[4] += f2.x * is; acc[5] += f2.y * is;
            acc[6] += f3.x * is; acc[7] += f3.y * is;
        }
    }

    float w[8];
    w[0] = acc[0] * __expf(-0.1f * t0.x);
    w[1] = acc[1] * __expf(-0.1f * t0.y);
    w[2] = acc[2] * __expf(-0.1f * t0.z);
    w[3] = acc[3] * __expf(-0.1f * t0.w);
    w[4] = acc[4] * __expf(-0.1f * t1.x);
    w[5] = acc[5] * __expf(-0.1f * t1.y);
    w[6] = acc[6] * __expf(-0.1f * t1.z);
    w[7] = acc[7] * __expf(-0.1f * t1.w);

    float lsum = 0.0f;
#pragma unroll
    for (int j = 0; j < 8; j++) lsum += w[j];
#pragma unroll
    for (int o = 16; o; o >>= 1) lsum += __shfl_xor_sync(0xFFFFFFFFu, lsum, o);
    if ((tid & 31) == 0) red[tid >> 5] = lsum;
    __syncthreads();
    if (tid == 0) {
        float t = 0.0f;
#pragma unroll
        for (int i = 0; i < 8; i++) t += red[i];
        red[0] = 1.0f / (t + 1e-8f);
    }
    __syncthreads();
    const float inv = red[0];

    float o[8];
#pragma unroll
    for (int j = 0; j < 8; j++) o[j] = w[j] * inv;
    __stcs((float4*)&attn[(size_t)bq * Lc + 8 * tid],
           make_float4(o[0], o[1], o[2], o[3]));
    __stcs((float4*)&attn[(size_t)bq * Lc + 8 * tid + 4],
           make_float4(o[4], o[5], o[6], o[7]));

    __half2 h0 = __floats2half2_rn(o[0], o[1]);
    __half2 h1 = __floats2half2_rn(o[2], o[3]);
    __half2 h2 = __floats2half2_rn(o[4], o[5]);
    __half2 h3 = __floats2half2_rn(o[6], o[7]);
    uint4 u;
    u.x = *(uint32_t*)&h0; u.y = *(uint32_t*)&h1;
    u.z = *(uint32_t*)&h2; u.w = *(uint32_t*)&h3;
    *(uint4*)&attnH[(size_t)bq * Lc + 8 * tid] = u;
}

// ---------------------------------------------------------------------------
extern "C" void kernel_launch(void* const* d_in, const int* in_sizes, int n_in,
                              void* d_out, int out_size)
{
    const float* x    = (const float*)d_in[0];   // [B,L,D]
    const float* td   = (const float*)d_in[1];   // [B,L,L]
    const float* W    = (const float*)d_in[2];   // [3D,D]
    const float* bias = (const float*)d_in[3];   // [3D]
    float* out = (float*)d_out;

    __half *qk, *S, *xh, *Wh, *xTh, *atnH;
    float *part, *attn_scratch;
    cudaGetSymbolAddress((void**)&qk, g_qk);
    cudaGetSymbolAddress((void**)&S, g_S);
    cudaGetSymbolAddress((void**)&xh, g_xh);
    cudaGetSymbolAddress((void**)&Wh, g_Wh);
    cudaGetSymbolAddress((void**)&xTh, g_xTh);
    cudaGetSymbolAddress((void**)&atnH, g_atnH);
    cudaGetSymbolAddress((void**)&part, g_part);
    cudaGetSymbolAddress((void**)&attn_scratch, g_attn);

    cudaFuncSetAttribute(gemm_h<0, float>,  cudaFuncAttributeMaxDynamicSharedMemorySize, SMEM_GEMM_BYTES);
    cudaFuncSetAttribute(gemm_h<1, __half>, cudaFuncAttributeMaxDynamicSharedMemorySize, SMEM_GEMM_BYTES);
    cudaFuncSetAttribute(gemm_exp_kernel,   cudaFuncAttributeMaxDynamicSharedMemorySize, SMEM_K2_BYTES);

    const long outElems  = (long)Bc * Lc * Dc;   // 4,194,304
    const long attnElems = (long)Bc * Lc * Lc;   // 8,388,608
    float* out_o = out;
    float* out_a = ((long)out_size >= outElems + attnElems) ? (out + outElems)
                                                            : attn_scratch;

    // P: fp16 copies of x, W[:2048] + fp16 x^T (single launch)
    prep_kernel<<<7168, 256>>>(x, W, xh, Wh, xTh);

    // K1: qk = fp16(xh @ Wh^T + bias)
    {
        dim3 grid(2 * Dc / 128, (Bc * Lc) / 128, 1);
        gemm_h<1, __half><<<grid, 512, SMEM_GEMM_BYTES>>>(
            xh, Dc, 0, 0,
            Wh, Dc, 0, 0,
            qk, 2 * Dc, 0, 0,
            1, Dc, 1.0f, bias);
    }

    // K2: S[b][q][h][k] = fp16(exp(0.125*Q@K^T - 6)) + per-tile row sums
    {
        dim3 grid(Lc / 128, Lc / 128, Bc * Hc);
        gemm_exp_kernel<<<grid, 512, SMEM_K2_BYTES>>>(qk, S, part);
    }

    // K4': gs-fold + head-mean + decay + renormalize -> attn fp32 + fp16
    attn_kernel<<<Bc * Lc, 256>>>(S, part, td, out_a, atnH);

    // K5: output = attnH @ xTh^T
    {
        dim3 grid(Dc / 128, Lc / 128, Bc);
        gemm_h<0, float><<<grid, 512, SMEM_GEMM_BYTES>>>(
            atnH, Lc, (long)Lc * Lc, 0,
            xTh,  Lc, (long)Dc * Lc, 0,
            out_o, Dc, (long)Lc * Dc, 0,
            1, Lc, 1.0f, nullptr);
    }
}

// round 14
// speedup vs baseline: 1.0185x; 1.0185x over previous
#include <cuda_runtime.h>
#include <cuda_fp16.h>
#include <cstdint>

// Problem constants
static constexpr int Bc  = 2;
static constexpr int Lc  = 2048;
static constexpr int Dc  = 1024;
static constexpr int Hc  = 16;

// Scratch (__device__ globals: allocation-free rule)
__device__ __half g_qk  [(size_t)Bc * Lc * 2 * Dc];     // [4096][2048] q|k fp16
__device__ __half g_S   [(size_t)Bc * Lc * Hc * Lc];    // exp(score-6) fp16, [b][q][h][k]
__device__ __half g_xh  [(size_t)Bc * Lc * Dc];         // x fp16
__device__ __half g_Wh  [(size_t)2 * Dc * Dc];          // W[:2048] fp16
__device__ __half g_xTh [(size_t)Bc * Dc * Lc];         // x^T fp16
__device__ __half g_atnH[(size_t)Bc * Lc * Lc];         // attn fp16 (K5 operand)
__device__ float  g_part[(size_t)Bc * Hc * 16 * Lc];    // per-ntile row sums
__device__ float  g_attn[(size_t)Bc * Lc * Lc];         // fallback attn buffer

// ---------------------------------------------------------------------------
__device__ __forceinline__ uint32_t smem_u32(const void* p) {
    uint32_t a;
    asm("{ .reg .u64 t; cvta.to.shared.u64 t, %1; cvt.u32.u64 %0, t; }" : "=r"(a) : "l"(p));
    return a;
}
__device__ __forceinline__ void mma16(float* c, const uint32_t* a, const uint32_t* b) {
    asm volatile(
        "mma.sync.aligned.m16n8k16.row.col.f32.f16.f16.f32 "
        "{%0,%1,%2,%3}, {%4,%5,%6,%7}, {%8,%9}, {%0,%1,%2,%3};"
        : "+f"(c[0]), "+f"(c[1]), "+f"(c[2]), "+f"(c[3])
        : "r"(a[0]), "r"(a[1]), "r"(a[2]), "r"(a[3]), "r"(b[0]), "r"(b[1]));
}
#define LDMX4(r0, r1, r2, r3, addr) \
    asm volatile("ldmatrix.sync.aligned.m8n8.x4.shared.b16 {%0,%1,%2,%3}, [%4];" \
        : "=r"(r0), "=r"(r1), "=r"(r2), "=r"(r3) : "r"(addr))
__device__ __forceinline__ void cp_async16(uint32_t dst, const void* src) {
    asm volatile("cp.async.cg.shared.global [%0], [%1], 16;" :: "r"(dst), "l"(src));
}
#define CP_COMMIT() asm volatile("cp.async.commit_group;" ::: "memory")
#define CP_WAIT(N)  asm volatile("cp.async.wait_group %0;" :: "n"(N) : "memory")

static constexpr int CHUNK = 64;
static constexpr int PADH  = 72;                        // 64 + 8 pad halves
static constexpr int AB_HALVES = 128 * PADH;            // 9216
static constexpr int STAGE_HALVES = 2 * AB_HALVES;      // A then B
static constexpr int NSTAGE = 3;
static constexpr int SMEM_GEMM_BYTES = NSTAGE * STAGE_HALVES * 2;   // 110592

// ---------------------------------------------------------------------------
// fp16 warp-MMA GEMM (K1/K5): C = f(alpha * A @ B^T)   [R12 best config]
// EPI: 0 = fp32 store (streaming), 1 = +bias -> fp16
// 256 thr = 8 warps (4m x 2n), warp tile 32x64, k-chunk 64, 3-stage ring.
// ---------------------------------------------------------------------------
template <int EPI, typename CT>
__global__ __launch_bounds__(256, 2)
void gemm_h(const __half* __restrict__ A, int lda, long aOut, long aIn,
            const __half* __restrict__ B, int ldb, long bOut, long bIn,
            CT* __restrict__ C, int ldc, long cOut, long cIn,
            int zInner, int Kd, float alpha, const float* __restrict__ bias)
{
    extern __shared__ __align__(16) char smemc[];
    const uint32_t sb = smem_u32(smemc);

    const int tid  = threadIdx.x;
    const int wid  = tid >> 5;
    const int lane = tid & 31;
    const int wm   = wid >> 1;
    const int wn   = wid & 1;
    const int lq   = lane >> 2;
    const int lr   = lane & 3;

    const int z  = blockIdx.z;
    const int zo = z / zInner, zi = z % zInner;
    A += (long)zo * aOut + (long)zi * aIn;
    B += (long)zo * bOut + (long)zi * bIn;
    C += (long)zo * cOut + (long)zi * cIn;

    const int m0 = blockIdx.y * 128;
    const int n0 = blockIdx.x * 128;

    float acc[2][8][4];
#pragma unroll
    for (int mt = 0; mt < 2; mt++)
#pragma unroll
        for (int nt = 0; nt < 8; nt++)
#pragma unroll
            for (int i = 0; i < 4; i++) acc[mt][nt][i] = 0.0f;

    const int nc = Kd / CHUNK;

    auto preload = [&](int c, int s) {
        const int k0 = c * CHUNK;
        const uint32_t abase = sb + (uint32_t)(s * STAGE_HALVES) * 2;
        const uint32_t bbase = abase + (uint32_t)AB_HALVES * 2;
#pragma unroll
        for (int j = 0; j < 4; j++) {
            const int f   = j * 256 + tid;
            const int row = f >> 3;
            const int c8  = f & 7;
            const uint32_t off = (uint32_t)(row * PADH + c8 * 8) * 2;
            cp_async16(abase + off, &A[(size_t)(m0 + row) * lda + k0 + c8 * 8]);
            cp_async16(bbase + off, &B[(size_t)(n0 + row) * ldb + k0 + c8 * 8]);
        }
    };

    preload(0, 0);
    CP_COMMIT();
    if (nc > 1) { preload(1, 1); CP_COMMIT(); }

    int s = 0;
    for (int c = 0; c < nc; c++) {
        if (c + 1 < nc) { CP_WAIT(1); } else { CP_WAIT(0); }
        __syncthreads();
        if (c + 2 < nc) {
            int s2 = s + 2; if (s2 >= NSTAGE) s2 -= NSTAGE;
            preload(c + 2, s2);
            CP_COMMIT();
        }

        const uint32_t stA = sb + (uint32_t)(s * STAGE_HALVES) * 2;
        const uint32_t stB = stA + (uint32_t)AB_HALVES * 2;

#pragma unroll
        for (int kh = 0; kh < CHUNK / 16; kh++) {
            uint32_t af[2][4];
#pragma unroll
            for (int mt = 0; mt < 2; mt++) {
                const int row = wm * 32 + mt * 16 + (lane & 7) + ((lane >> 3) & 1) * 8;
                const int col = kh * 16 + (lane >> 4) * 8;
                LDMX4(af[mt][0], af[mt][1], af[mt][2], af[mt][3],
                      stA + (uint32_t)(row * PADH + col) * 2);
            }
#pragma unroll
            for (int np = 0; np < 4; np++) {
                const int rowb = wn * 64 + np * 16 + (lane >> 4) * 8 + (lane & 7);
                const int colk = kh * 16 + ((lane >> 3) & 1) * 8;
                uint32_t bf[4];
                LDMX4(bf[0], bf[1], bf[2], bf[3],
                      stB + (uint32_t)(rowb * PADH + colk) * 2);
                mma16(acc[0][np * 2    ], af[0], bf + 0);
                mma16(acc[1][np * 2    ], af[1], bf + 0);
                mma16(acc[0][np * 2 + 1], af[0], bf + 2);
                mma16(acc[1][np * 2 + 1], af[1], bf + 2);
            }
        }
        if (++s >= NSTAGE) s -= NSTAGE;
    }
    __syncthreads();

    // ---- epilogue: regs -> fp32 staged smem -> coalesced GMEM ----
    float* stg = (float*)smemc;                        // 128 x 132 floats
#pragma unroll
    for (int mt = 0; mt < 2; mt++) {
        const int r = wm * 32 + mt * 16 + lq;
#pragma unroll
        for (int nt = 0; nt < 8; nt++) {
            const int cI = wn * 64 + nt * 8 + 2 * lr;
            *(float2*)&stg[(r    ) * 132 + cI] =
                make_float2(acc[mt][nt][0] * alpha, acc[mt][nt][1] * alpha);
            *(float2*)&stg[(r + 8) * 132 + cI] =
                make_float2(acc[mt][nt][2] * alpha, acc[mt][nt][3] * alpha);
        }
    }
    __syncthreads();

    float4 bv = make_float4(0.f, 0.f, 0.f, 0.f);
    if (EPI == 1) bv = *(const float4*)&bias[n0 + lane * 4];
#pragma unroll
    for (int it = 0; it < 16; it++) {
        const int r2 = it * 8 + wid;
        float4 v = *(const float4*)&stg[r2 * 132 + lane * 4];
        if (EPI == 1) { v.x += bv.x; v.y += bv.y; v.z += bv.z; v.w += bv.w; }
        if (EPI == 0) {
            __stcs((float4*)&C[(size_t)(m0 + r2) * ldc + n0 + lane * 4], v);
        } else {
            __half2 h0 = __floats2half2_rn(v.x, v.y);
            __half2 h1 = __floats2half2_rn(v.z, v.w);
            uint2 u;
            u.x = *(uint32_t*)&h0; u.y = *(uint32_t*)&h1;
            *(uint2*)&C[(size_t)(m0 + r2) * ldc + n0 + lane * 4] = u;
        }
    }
}

// ---------------------------------------------------------------------------
// K2: dedicated scores kernel (R11/R12 config, unchanged).
// ---------------------------------------------------------------------------
static constexpr int PADS = 136;                        // staging halves/row
static constexpr int SMEM_K2_BYTES = STAGE_HALVES * 2;  // 36864 (one stage)

__global__ __launch_bounds__(512, 2)
void gemm_exp_kernel(const __half* __restrict__ qk, __half* __restrict__ S,
                     float* __restrict__ partial)
{
    extern __shared__ __align__(16) char smemc[];
    const uint32_t sb = smem_u32(smemc);

    const int tid  = threadIdx.x;
    const int wid  = tid >> 5;          // 0..15
    const int lane = tid & 31;
    const int wm   = wid >> 2;          // 0..3
    const int wn   = wid & 3;           // 0..3
    const int lq   = lane >> 2;         // 0..7
    const int lr   = lane & 3;          // 0..3

    const int z = blockIdx.z;           // b*16 + h
    const int b = z >> 4, h = z & 15;
    const int m0 = blockIdx.y * 128;    // q base
    const int n0 = blockIdx.x * 128;    // k base

    const __half* A = qk + (size_t)b * Lc * 2 * Dc + (size_t)h * 64;   // q
    const __half* B = A + Dc;                                          // k
    const int ld = 2 * Dc;

    {
        const uint32_t abase = sb;
        const uint32_t bbase = sb + (uint32_t)AB_HALVES * 2;
#pragma unroll
        for (int j = 0; j < 2; j++) {
            const int f   = j * 512 + tid;
            const int row = f >> 3;
            const int c8  = f & 7;
            const uint32_t off = (uint32_t)(row * PADH + c8 * 8) * 2;
            cp_async16(abase + off, &A[(size_t)(m0 + row) * ld + c8 * 8]);
            cp_async16(bbase + off, &B[(size_t)(n0 + row) * ld + c8 * 8]);
        }
    }
    CP_COMMIT();
    CP_WAIT(0);
    __syncthreads();

    float acc[2][4][4];
#pragma unroll
    for (int mt = 0; mt < 2; mt++)
#pragma unroll
        for (int nt = 0; nt < 4; nt++)
#pragma unroll
            for (int i = 0; i < 4; i++) acc[mt][nt][i] = 0.0f;

    const uint32_t stA = sb;
    const uint32_t stB = sb + (uint32_t)AB_HALVES * 2;

#pragma unroll
    for (int kh = 0; kh < 4; kh++) {
        uint32_t af[2][4];
#pragma unroll
        for (int mt = 0; mt < 2; mt++) {
            const int row = wm * 32 + mt * 16 + (lane & 7) + ((lane >> 3) & 1) * 8;
            const int col = kh * 16 + (lane >> 4) * 8;
            LDMX4(af[mt][0], af[mt][1], af[mt][2], af[mt][3],
                  stA + (uint32_t)(row * PADH + col) * 2);
        }
#pragma unroll
        for (int np = 0; np < 2; np++) {
            const int rowb = wn * 32 + np * 16 + (lane >> 4) * 8 + (lane & 7);
            const int colk = kh * 16 + ((lane >> 3) & 1) * 8;
            uint32_t bf[4];
            LDMX4(bf[0], bf[1], bf[2], bf[3],
                  stB + (uint32_t)(rowb * PADH + colk) * 2);
            mma16(acc[0][np * 2    ], af[0], bf + 0);
            mma16(acc[1][np * 2    ], af[1], bf + 0);
            mma16(acc[0][np * 2 + 1], af[0], bf + 2);
            mma16(acc[1][np * 2 + 1], af[1], bf + 2);
        }
    }
    __syncthreads();            // operand smem about to be reused as staging

    // exp + fp16 staging
    __half* stgh = (__half*)smemc;      // 128 x PADS halves
#pragma unroll
    for (int mt = 0; mt < 2; mt++) {
        const int r = wm * 32 + mt * 16 + lq;
#pragma unroll
        for (int nt = 0; nt < 4; nt++) {
            const int cI = wn * 32 + nt * 8 + 2 * lr;
            float v0 = __expf(0.125f * acc[mt][nt][0] - 6.0f);
            float v1 = __expf(0.125f * acc[mt][nt][1] - 6.0f);
            float v2 = __expf(0.125f * acc[mt][nt][2] - 6.0f);
            float v3 = __expf(0.125f * acc[mt][nt][3] - 6.0f);
            *(__half2*)&stgh[(r    ) * PADS + cI] = __floats2half2_rn(v0, v1);
            *(__half2*)&stgh[(r + 8) * PADS + cI] = __floats2half2_rn(v2, v3);
        }
    }
    __syncthreads();

    // per-row partial sums (4 threads/row, 32 halves each, shfl-reduce)
    {
        const int row = tid >> 2;
        const int q4  = tid & 3;
        float sum = 0.0f;
#pragma unroll
        for (int j = 0; j < 4; j++) {
            const uint4 u = *(const uint4*)&stgh[row * PADS + q4 * 32 + j * 8];
            float2 f0 = __half22float2(*(const __half2*)&u.x);
            float2 f1 = __half22float2(*(const __half2*)&u.y);
            float2 f2 = __half22float2(*(const __half2*)&u.z);
            float2 f3 = __half22float2(*(const __half2*)&u.w);
            sum += f0.x + f0.y + f1.x + f1.y + f2.x + f2.y + f3.x + f3.y;
        }
        sum += __shfl_xor_sync(0xFFFFFFFFu, sum, 1);
        sum += __shfl_xor_sync(0xFFFFFFFFu, sum, 2);
        if (q4 == 0)
            partial[(size_t)(z * 16 + blockIdx.x) * Lc + m0 + row] = sum;
    }

    // store S (streaming, evict-first): [b][q][h][k]; 2048 uint4 slots
#pragma unroll
    for (int it = 0; it < 4; it++) {
        const int slot = tid + it * 512;
        const int row  = slot >> 4;
        const int c16  = slot & 15;
        const uint4 u = *(const uint4*)&stgh[row * PADS + c16 * 8];
        __stcs((uint4*)&S[(((size_t)b * Lc + m0 + row) * Hc + h) * Lc + n0 + c16 * 8], u);
    }
}

// ---------------------------------------------------------------------------
// Combined prep kernel (one launch)
// ---------------------------------------------------------------------------
__global__ __launch_bounds__(256)
void prep_kernel(const float* __restrict__ x, const float* __restrict__ W,
                 __half* __restrict__ xh, __half* __restrict__ Wh,
                 __half* __restrict__ xTh)
{
    const int bid = blockIdx.x;
    const int tid = threadIdx.x;

    if (bid < 3072) {
        const float* src = (bid < 2048) ? x : W;
        __half* dst      = (bid < 2048) ? xh : Wh;
        const size_t base = (size_t)(bid < 2048 ? bid : bid - 2048) * 2048;
        const size_t i = base + (size_t)tid * 8;
        float4 a = *(const float4*)&src[i];
        float4 b = *(const float4*)&src[i + 4];
        __half2 h0 = __floats2half2_rn(a.x, a.y);
        __half2 h1 = __floats2half2_rn(a.z, a.w);
        __half2 h2 = __floats2half2_rn(b.x, b.y);
        __half2 h3 = __floats2half2_rn(b.z, b.w);
        uint4 u;
        u.x = *(uint32_t*)&h0; u.y = *(uint32_t*)&h1;
        u.z = *(uint32_t*)&h2; u.w = *(uint32_t*)&h3;
        *(uint4*)&dst[i] = u;
        return;
    }

    __shared__ float t[32][33];
    const int r  = bid - 3072;
    const int b  = r >> 11;
    const int rr = r & 2047;
    const int l0 = (rr >> 5) * 32;
    const int d0 = (rr & 31) * 32;
    const int tx = tid & 31;
    const int ty = tid >> 5;
#pragma unroll
    for (int j = 0; j < 4; j++)
        t[ty + 8 * j][tx] = x[(size_t)b * Lc * Dc + (size_t)(l0 + ty + 8 * j) * Dc + d0 + tx];
    __syncthreads();
#pragma unroll
    for (int j = 0; j < 4; j++)
        xTh[(size_t)b * Dc * Lc + (size_t)(d0 + ty + 8 * j) * Lc + l0 + tx] =
            __float2half_rn(t[tx][ty + 8 * j]);
}

// ---------------------------------------------------------------------------
// K4': gs-fold + head-mean + decay + renormalize.
// store_f32 == 0 -> skip fp32 attn stores (scratch case: nobody reads them).
// ---------------------------------------------------------------------------
__global__ __launch_bounds__(256)
void attn_kernel(const __half* __restrict__ E, const float* __restrict__ part,
                 const float* __restrict__ td, float* __restrict__ attn,
                 __half* __restrict__ attnH, int store_f32)
{
    const int bq = blockIdx.x;
    const int b  = bq >> 11;
    const int q  = bq & (Lc - 1);
    const int tid = threadIdx.x;

    __shared__ float red2[256];
    __shared__ float ish[Hc];
    __shared__ float red[8];

    {
        const int h = tid >> 4, kt = tid & 15;
        red2[tid] = part[((size_t)((b * Hc + h) * 16 + kt)) * Lc + q];
    }
    __syncthreads();
    if (tid < Hc) {
        float s = 0.0f;
#pragma unroll
        for (int kt = 0; kt < 16; kt++) s += red2[tid * 16 + kt];
        ish[tid] = 1.0f / (16.0f * s);
    }
    __syncthreads();

    const __half* Eq = E + (size_t)bq * Hc * Lc;

    const float4 t0 = __ldcs((const float4*)&td[(size_t)bq * Lc + 8 * tid]);
    const float4 t1 = __ldcs((const float4*)&td[(size_t)bq * Lc + 8 * tid + 4]);

    float acc[8];
#pragma unroll
    for (int j = 0; j < 8; j++) acc[j] = 0.0f;

#pragma unroll
    for (int hb = 0; hb < Hc; hb += 4) {
        uint4 u[4];
#pragma unroll
        for (int i = 0; i < 4; i++)
            u[i] = __ldcs((const uint4*)&Eq[(size_t)(hb + i) * Lc + 8 * tid]);
#pragma unroll
        for (int i = 0; i < 4; i++) {
            const float is = ish[hb + i];
            float2 f0 = __half22float2(*(const __half2*)&u[i].x);
            float2 f1 = __half22float2(*(const __half2*)&u[i].y);
            float2 f2 = __half22float2(*(const __half2*)&u[i].z);
            float2 f3 = __half22float2(*(const __half2*)&u[i].w);
            acc[0] += f0.x * is; acc[1] += f0.y * is;
            acc[2] += f1.x * is; acc[3] += f1.y * is;
            acc[4] += f2.x * is; acc[5] += f2.y * is;
            acc[6] += f3.x * is; acc[7] += f3.y * is;
        }
    }

    float w[8];
    w[0] = acc[0] * __expf(-0.1f * t0.x);
    w[1] = acc[1] * __expf(-0.1f * t0.y);
    w[2] = acc[2] * __expf(-0.1f * t0.z);
    w[3] = acc[3] * __expf(-0.1f * t0.w);
    w[4] = acc[4] * __expf(-0.1f * t1.x);
    w[5] = acc[5] * __expf(-0.1f * t1.y);
    w[6] = acc[6] * __expf(-0.1f * t1.z);
    w[7] = acc[7] * __expf(-0.1f * t1.w);

    float lsum = 0.0f;
#pragma unroll
    for (int j = 0; j < 8; j++) lsum += w[j];
#pragma unroll
    for (int o = 16; o; o >>= 1) lsum += __shfl_xor_sync(0xFFFFFFFFu, lsum, o);
    if ((tid & 31) == 0) red[tid >> 5] = lsum;
    __syncthreads();
    if (tid == 0) {
        float t = 0.0f;
#pragma unroll
        for (int i = 0; i < 8; i++) t += red[i];
        red[0] = 1.0f / (t + 1e-8f);
    }
    __syncthreads();
    const float inv = red[0];

    float o[8];
#pragma unroll
    for (int j = 0; j < 8; j++) o[j] = w[j] * inv;
    if (store_f32) {
        __stcs((float4*)&attn[(size_t)bq * Lc + 8 * tid],
               make_float4(o[0], o[1], o[2], o[3]));
        __stcs((float4*)&attn[(size_t)bq * Lc + 8 * tid + 4],
               make_float4(o[4], o[5], o[6], o[7]));
    }

    __half2 h0 = __floats2half2_rn(o[0], o[1]);
    __half2 h1 = __floats2half2_rn(o[2], o[3]);
    __half2 h2 = __floats2half2_rn(o[4], o[5]);
    __half2 h3 = __floats2half2_rn(o[6], o[7]);
    uint4 u;
    u.x = *(uint32_t*)&h0; u.y = *(uint32_t*)&h1;
    u.z = *(uint32_t*)&h2; u.w = *(uint32_t*)&h3;
    *(uint4*)&attnH[(size_t)bq * Lc + 8 * tid] = u;
}

// ---------------------------------------------------------------------------
extern "C" void kernel_launch(void* const* d_in, const int* in_sizes, int n_in,
                              void* d_out, int out_size)
{
    const float* x    = (const float*)d_in[0];   // [B,L,D]
    const float* td   = (const float*)d_in[1];   // [B,L,L]
    const float* W    = (const float*)d_in[2];   // [3D,D]
    const float* bias = (const float*)d_in[3];   // [3D]
    float* out = (float*)d_out;

    __half *qk, *S, *xh, *Wh, *xTh, *atnH;
    float *part, *attn_scratch;
    cudaGetSymbolAddress((void**)&qk, g_qk);
    cudaGetSymbolAddress((void**)&S, g_S);
    cudaGetSymbolAddress((void**)&xh, g_xh);
    cudaGetSymbolAddress((void**)&Wh, g_Wh);
    cudaGetSymbolAddress((void**)&xTh, g_xTh);
    cudaGetSymbolAddress((void**)&atnH, g_atnH);
    cudaGetSymbolAddress((void**)&part, g_part);
    cudaGetSymbolAddress((void**)&attn_scratch, g_attn);

    cudaFuncSetAttribute(gemm_h<0, float>,  cudaFuncAttributeMaxDynamicSharedMemorySize, SMEM_GEMM_BYTES);
    cudaFuncSetAttribute(gemm_h<1, __half>, cudaFuncAttributeMaxDynamicSharedMemorySize, SMEM_GEMM_BYTES);
    cudaFuncSetAttribute(gemm_exp_kernel,   cudaFuncAttributeMaxDynamicSharedMemorySize, SMEM_K2_BYTES);

    const long outElems  = (long)Bc * Lc * Dc;   // 4,194,304
    const long attnElems = (long)Bc * Lc * Lc;   // 8,388,608
    const bool wantAttn = ((long)out_size >= outElems + attnElems);
    float* out_o = out;
    float* out_a = wantAttn ? (out + outElems) : attn_scratch;

    // P: fp16 copies of x, W[:2048] + fp16 x^T (single launch)
    prep_kernel<<<7168, 256>>>(x, W, xh, Wh, xTh);

    // K1: qk = fp16(xh @ Wh^T + bias)
    {
        dim3 grid(2 * Dc / 128, (Bc * Lc) / 128, 1);
        gemm_h<1, __half><<<grid, 256, SMEM_GEMM_BYTES>>>(
            xh, Dc, 0, 0,
            Wh, Dc, 0, 0,
            qk, 2 * Dc, 0, 0,
            1, Dc, 1.0f, bias);
    }

    // K2: S[b][q][h][k] = fp16(exp(0.125*Q@K^T - 6)) + per-tile row sums
    {
        dim3 grid(Lc / 128, Lc / 128, Bc * Hc);
        gemm_exp_kernel<<<grid, 512, SMEM_K2_BYTES>>>(qk, S, part);
    }

    // K4': gs-fold + head-mean + decay + renormalize -> attnH (+fp32 if wanted)
    attn_kernel<<<Bc * Lc, 256>>>(S, part, td, out_a, atnH, wantAttn ? 1 : 0);

    // K5: output = attnH @ xTh^T
    {
        dim3 grid(Dc / 128, Lc / 128, Bc);
        gemm_h<0, float><<<grid, 256, SMEM_GEMM_BYTES>>>(
            atnH, Lc, (long)Lc * Lc, 0,
            xTh,  Lc, (long)Dc * Lc, 0,
            out_o, Dc, (long)Lc * Dc, 0,
            1, Lc, 1.0f, nullptr);
    }
}

// round 15
// speedup vs baseline: 1.0612x; 1.0419x over previous
#include <cuda_runtime.h>
#include <cuda_fp16.h>
#include <cstdint>

// Problem constants
static constexpr int Bc  = 2;
static constexpr int Lc  = 2048;
static constexpr int Dc  = 1024;
static constexpr int Hc  = 16;

// Scratch (__device__ globals: allocation-free rule)
__device__ __half g_qk  [(size_t)Bc * Lc * 2 * Dc];     // [4096][2048] q|k fp16
__device__ __half g_S   [(size_t)Bc * Lc * Hc * Lc];    // exp(score-6) fp16, [b][q][h][k]
__device__ __half g_xh  [(size_t)Bc * Lc * Dc];         // x fp16
__device__ __half g_Wh  [(size_t)2 * Dc * Dc];          // W[:2048] fp16
__device__ __half g_xTh [(size_t)Bc * Dc * Lc];         // x^T fp16
__device__ __half g_atnH[(size_t)Bc * Lc * Lc];         // attn fp16 (K5 operand)
__device__ float  g_part[(size_t)Bc * Hc * 16 * Lc];    // per-ktile row sums
__device__ float  g_attn[(size_t)Bc * Lc * Lc];         // fallback attn buffer

// ---------------------------------------------------------------------------
__device__ __forceinline__ uint32_t smem_u32(const void* p) {
    uint32_t a;
    asm("{ .reg .u64 t; cvta.to.shared.u64 t, %1; cvt.u32.u64 %0, t; }" : "=r"(a) : "l"(p));
    return a;
}
__device__ __forceinline__ void mma16(float* c, const uint32_t* a, const uint32_t* b) {
    asm volatile(
        "mma.sync.aligned.m16n8k16.row.col.f32.f16.f16.f32 "
        "{%0,%1,%2,%3}, {%4,%5,%6,%7}, {%8,%9}, {%0,%1,%2,%3};"
        : "+f"(c[0]), "+f"(c[1]), "+f"(c[2]), "+f"(c[3])
        : "r"(a[0]), "r"(a[1]), "r"(a[2]), "r"(a[3]), "r"(b[0]), "r"(b[1]));
}
#define LDMX4(r0, r1, r2, r3, addr) \
    asm volatile("ldmatrix.sync.aligned.m8n8.x4.shared.b16 {%0,%1,%2,%3}, [%4];" \
        : "=r"(r0), "=r"(r1), "=r"(r2), "=r"(r3) : "r"(addr))
__device__ __forceinline__ void cp_async16(uint32_t dst, const void* src) {
    asm volatile("cp.async.cg.shared.global [%0], [%1], 16;" :: "r"(dst), "l"(src));
}
#define CP_COMMIT() asm volatile("cp.async.commit_group;" ::: "memory")
#define CP_WAIT(N)  asm volatile("cp.async.wait_group %0;" :: "n"(N) : "memory")

static constexpr int CHUNK = 64;
static constexpr int PADH  = 72;                        // 64 + 8 pad halves
static constexpr int AB_HALVES = 128 * PADH;            // 9216
static constexpr int STAGE_HALVES = 2 * AB_HALVES;      // A then B
static constexpr int NSTAGE = 3;
static constexpr int SMEM_GEMM_BYTES = NSTAGE * STAGE_HALVES * 2;   // 110592

// ---------------------------------------------------------------------------
// fp16 warp-MMA GEMM (K1/K5): C = f(alpha * A @ B^T)   [R12 best config]
// EPI: 0 = fp32 store (streaming), 1 = +bias -> fp16
// 256 thr = 8 warps (4m x 2n), warp tile 32x64, k-chunk 64, 3-stage ring.
// ---------------------------------------------------------------------------
template <int EPI, typename CT>
__global__ __launch_bounds__(256, 2)
void gemm_h(const __half* __restrict__ A, int lda, long aOut, long aIn,
            const __half* __restrict__ B, int ldb, long bOut, long bIn,
            CT* __restrict__ C, int ldc, long cOut, long cIn,
            int zInner, int Kd, float alpha, const float* __restrict__ bias)
{
    extern __shared__ __align__(16) char smemc[];
    const uint32_t sb = smem_u32(smemc);

    const int tid  = threadIdx.x;
    const int wid  = tid >> 5;
    const int lane = tid & 31;
    const int wm   = wid >> 1;
    const int wn   = wid & 1;
    const int lq   = lane >> 2;
    const int lr   = lane & 3;

    const int z  = blockIdx.z;
    const int zo = z / zInner, zi = z % zInner;
    A += (long)zo * aOut + (long)zi * aIn;
    B += (long)zo * bOut + (long)zi * bIn;
    C += (long)zo * cOut + (long)zi * cIn;

    const int m0 = blockIdx.y * 128;
    const int n0 = blockIdx.x * 128;

    float acc[2][8][4];
#pragma unroll
    for (int mt = 0; mt < 2; mt++)
#pragma unroll
        for (int nt = 0; nt < 8; nt++)
#pragma unroll
            for (int i = 0; i < 4; i++) acc[mt][nt][i] = 0.0f;

    const int nc = Kd / CHUNK;

    auto preload = [&](int c, int s) {
        const int k0 = c * CHUNK;
        const uint32_t abase = sb + (uint32_t)(s * STAGE_HALVES) * 2;
        const uint32_t bbase = abase + (uint32_t)AB_HALVES * 2;
#pragma unroll
        for (int j = 0; j < 4; j++) {
            const int f   = j * 256 + tid;
            const int row = f >> 3;
            const int c8  = f & 7;
            const uint32_t off = (uint32_t)(row * PADH + c8 * 8) * 2;
            cp_async16(abase + off, &A[(size_t)(m0 + row) * lda + k0 + c8 * 8]);
            cp_async16(bbase + off, &B[(size_t)(n0 + row) * ldb + k0 + c8 * 8]);
        }
    };

    preload(0, 0);
    CP_COMMIT();
    if (nc > 1) { preload(1, 1); CP_COMMIT(); }

    int s = 0;
    for (int c = 0; c < nc; c++) {
        if (c + 1 < nc) { CP_WAIT(1); } else { CP_WAIT(0); }
        __syncthreads();
        if (c + 2 < nc) {
            int s2 = s + 2; if (s2 >= NSTAGE) s2 -= NSTAGE;
            preload(c + 2, s2);
            CP_COMMIT();
        }

        const uint32_t stA = sb + (uint32_t)(s * STAGE_HALVES) * 2;
        const uint32_t stB = stA + (uint32_t)AB_HALVES * 2;

#pragma unroll
        for (int kh = 0; kh < CHUNK / 16; kh++) {
            uint32_t af[2][4];
#pragma unroll
            for (int mt = 0; mt < 2; mt++) {
                const int row = wm * 32 + mt * 16 + (lane & 7) + ((lane >> 3) & 1) * 8;
                const int col = kh * 16 + (lane >> 4) * 8;
                LDMX4(af[mt][0], af[mt][1], af[mt][2], af[mt][3],
                      stA + (uint32_t)(row * PADH + col) * 2);
            }
#pragma unroll
            for (int np = 0; np < 4; np++) {
                const int rowb = wn * 64 + np * 16 + (lane >> 4) * 8 + (lane & 7);
                const int colk = kh * 16 + ((lane >> 3) & 1) * 8;
                uint32_t bf[4];
                LDMX4(bf[0], bf[1], bf[2], bf[3],
                      stB + (uint32_t)(rowb * PADH + colk) * 2);
                mma16(acc[0][np * 2    ], af[0], bf + 0);
                mma16(acc[1][np * 2    ], af[1], bf + 0);
                mma16(acc[0][np * 2 + 1], af[0], bf + 2);
                mma16(acc[1][np * 2 + 1], af[1], bf + 2);
            }
        }
        if (++s >= NSTAGE) s -= NSTAGE;
    }
    __syncthreads();

    // ---- epilogue: regs -> fp32 staged smem -> coalesced GMEM ----
    float* stg = (float*)smemc;                        // 128 x 132 floats
#pragma unroll
    for (int mt = 0; mt < 2; mt++) {
        const int r = wm * 32 + mt * 16 + lq;
#pragma unroll
        for (int nt = 0; nt < 8; nt++) {
            const int cI = wn * 64 + nt * 8 + 2 * lr;
            *(float2*)&stg[(r    ) * 132 + cI] =
                make_float2(acc[mt][nt][0] * alpha, acc[mt][nt][1] * alpha);
            *(float2*)&stg[(r + 8) * 132 + cI] =
                make_float2(acc[mt][nt][2] * alpha, acc[mt][nt][3] * alpha);
        }
    }
    __syncthreads();

    float4 bv = make_float4(0.f, 0.f, 0.f, 0.f);
    if (EPI == 1) bv = *(const float4*)&bias[n0 + lane * 4];
#pragma unroll
    for (int it = 0; it < 16; it++) {
        const int r2 = it * 8 + wid;
        float4 v = *(const float4*)&stg[r2 * 132 + lane * 4];
        if (EPI == 1) { v.x += bv.x; v.y += bv.y; v.z += bv.z; v.w += bv.w; }
        if (EPI == 0) {
            __stcs((float4*)&C[(size_t)(m0 + r2) * ldc + n0 + lane * 4], v);
        } else {
            __half2 h0 = __floats2half2_rn(v.x, v.y);
            __half2 h1 = __floats2half2_rn(v.z, v.w);
            uint2 u;
            u.x = *(uint32_t*)&h0; u.y = *(uint32_t*)&h1;
            *(uint2*)&C[(size_t)(m0 + r2) * ldc + n0 + lane * 4] = u;
        }
    }
}

// ---------------------------------------------------------------------------
// K2: dedicated scores kernel — 64x128 tile, 256 thr = 8 warps (2m x 4n),
// warp tile 32x32, single K=64 chunk, launch_bounds(256,4) -> 4 CTA/SM for
// cross-CTA overlap of load/MMA/exp/store phases. Same per-row partial-sum
// grouping and S values as before (bit-identical numerics).
// ---------------------------------------------------------------------------
static constexpr int PADS = 136;                          // staging halves/row
static constexpr int A64_HALVES = 64 * PADH;              // 4608
static constexpr int B64_HALVES = 128 * PADH;             // 9216
static constexpr int SMEM_K2_BYTES = (A64_HALVES + B64_HALVES) * 2;   // 27648
// staging needs 64*136*2 = 17408 <= 27648  OK

__global__ __launch_bounds__(256, 4)
void gemm_exp_kernel(const __half* __restrict__ qk, __half* __restrict__ S,
                     float* __restrict__ partial)
{
    extern __shared__ __align__(16) char smemc[];
    const uint32_t sb = smem_u32(smemc);

    const int tid  = threadIdx.x;
    const int wid  = tid >> 5;          // 0..7
    const int lane = tid & 31;
    const int wm   = wid >> 2;          // 0..1  (m: 64 rows)
    const int wn   = wid & 3;           // 0..3  (n: 128 cols)
    const int lq   = lane >> 2;         // 0..7
    const int lr   = lane & 3;          // 0..3

    const int z = blockIdx.z;           // b*16 + h
    const int b = z >> 4, h = z & 15;
    const int m0 = blockIdx.y * 64;     // q base (64-tile)
    const int n0 = blockIdx.x * 128;    // k base

    const __half* A = qk + (size_t)b * Lc * 2 * Dc + (size_t)h * 64;   // q
    const __half* B = A + Dc;                                          // k
    const int ld = 2 * Dc;

    const uint32_t abase = sb;
    const uint32_t bbase = sb + (uint32_t)A64_HALVES * 2;

    // load A (64x64) + B (128x64) tiles
    {
#pragma unroll
        for (int j = 0; j < 2; j++) {               // A: 512 float4 slots
            const int f   = j * 256 + tid;
            const int row = f >> 3;
            const int c8  = f & 7;
            cp_async16(abase + (uint32_t)(row * PADH + c8 * 8) * 2,
                       &A[(size_t)(m0 + row) * ld + c8 * 8]);
        }
#pragma unroll
        for (int j = 0; j < 4; j++) {               // B: 1024 float4 slots
            const int f   = j * 256 + tid;
            const int row = f >> 3;
            const int c8  = f & 7;
            cp_async16(bbase + (uint32_t)(row * PADH + c8 * 8) * 2,
                       &B[(size_t)(n0 + row) * ld + c8 * 8]);
        }
    }
    CP_COMMIT();
    CP_WAIT(0);
    __syncthreads();

    float acc[2][4][4];
#pragma unroll
    for (int mt = 0; mt < 2; mt++)
#pragma unroll
        for (int nt = 0; nt < 4; nt++)
#pragma unroll
            for (int i = 0; i < 4; i++) acc[mt][nt][i] = 0.0f;

#pragma unroll
    for (int kh = 0; kh < 4; kh++) {
        uint32_t af[2][4];
#pragma unroll
        for (int mt = 0; mt < 2; mt++) {
            const int row = wm * 32 + mt * 16 + (lane & 7) + ((lane >> 3) & 1) * 8;
            const int col = kh * 16 + (lane >> 4) * 8;
            LDMX4(af[mt][0], af[mt][1], af[mt][2], af[mt][3],
                  abase + (uint32_t)(row * PADH + col) * 2);
        }
#pragma unroll
        for (int np = 0; np < 2; np++) {
            const int rowb = wn * 32 + np * 16 + (lane >> 4) * 8 + (lane & 7);
            const int colk = kh * 16 + ((lane >> 3) & 1) * 8;
            uint32_t bf[4];
            LDMX4(bf[0], bf[1], bf[2], bf[3],
                  bbase + (uint32_t)(rowb * PADH + colk) * 2);
            mma16(acc[0][np * 2    ], af[0], bf + 0);
            mma16(acc[1][np * 2    ], af[1], bf + 0);
            mma16(acc[0][np * 2 + 1], af[0], bf + 2);
            mma16(acc[1][np * 2 + 1], af[1], bf + 2);
        }
    }
    __syncthreads();            // operand smem about to be reused as staging

    // exp + fp16 staging (64 x PADS halves)
    __half* stgh = (__half*)smemc;
#pragma unroll
    for (int mt = 0; mt < 2; mt++) {
        const int r = wm * 32 + mt * 16 + lq;
#pragma unroll
        for (int nt = 0; nt < 4; nt++) {
            const int cI = wn * 32 + nt * 8 + 2 * lr;
            float v0 = __expf(0.125f * acc[mt][nt][0] - 6.0f);
            float v1 = __expf(0.125f * acc[mt][nt][1] - 6.0f);
            float v2 = __expf(0.125f * acc[mt][nt][2] - 6.0f);
            float v3 = __expf(0.125f * acc[mt][nt][3] - 6.0f);
            *(__half2*)&stgh[(r    ) * PADS + cI] = __floats2half2_rn(v0, v1);
            *(__half2*)&stgh[(r + 8) * PADS + cI] = __floats2half2_rn(v2, v3);
        }
    }
    __syncthreads();

    // per-row partial sums (4 threads/row over 128 cols -> same values as before)
    {
        const int row = tid >> 2;       // 0..63
        const int q4  = tid & 3;
        float sum = 0.0f;
#pragma unroll
        for (int j = 0; j < 4; j++) {
            const uint4 u = *(const uint4*)&stgh[row * PADS + q4 * 32 + j * 8];
            float2 f0 = __half22float2(*(const __half2*)&u.x);
            float2 f1 = __half22float2(*(const __half2*)&u.y);
            float2 f2 = __half22float2(*(const __half2*)&u.z);
            float2 f3 = __half22float2(*(const __half2*)&u.w);
            sum += f0.x + f0.y + f1.x + f1.y + f2.x + f2.y + f3.x + f3.y;
        }
        sum += __shfl_xor_sync(0xFFFFFFFFu, sum, 1);
        sum += __shfl_xor_sync(0xFFFFFFFFu, sum, 2);
        if (q4 == 0)
            partial[(size_t)(z * 16 + blockIdx.x) * Lc + m0 + row] = sum;
    }

    // store S (streaming): [b][q][h][k]; 64x128 halves = 1024 uint4 slots
#pragma unroll
    for (int it = 0; it < 4; it++) {
        const int slot = tid + it * 256;
        const int row  = slot >> 4;
        const int c16  = slot & 15;
        const uint4 u = *(const uint4*)&stgh[row * PADS + c16 * 8];
        __stcs((uint4*)&S[(((size_t)b * Lc + m0 + row) * Hc + h) * Lc + n0 + c16 * 8], u);
    }
}

// ---------------------------------------------------------------------------
// Combined prep kernel (one launch)
// ---------------------------------------------------------------------------
__global__ __launch_bounds__(256)
void prep_kernel(const float* __restrict__ x, const float* __restrict__ W,
                 __half* __restrict__ xh, __half* __restrict__ Wh,
                 __half* __restrict__ xTh)
{
    const int bid = blockIdx.x;
    const int tid = threadIdx.x;

    if (bid < 3072) {
        const float* src = (bid < 2048) ? x : W;
        __half* dst      = (bid < 2048) ? xh : Wh;
        const size_t base = (size_t)(bid < 2048 ? bid : bid - 2048) * 2048;
        const size_t i = base + (size_t)tid * 8;
        float4 a = *(const float4*)&src[i];
        float4 b = *(const float4*)&src[i + 4];
        __half2 h0 = __floats2half2_rn(a.x, a.y);
        __half2 h1 = __floats2half2_rn(a.z, a.w);
        __half2 h2 = __floats2half2_rn(b.x, b.y);
        __half2 h3 = __floats2half2_rn(b.z, b.w);
        uint4 u;
        u.x = *(uint32_t*)&h0; u.y = *(uint32_t*)&h1;
        u.z = *(uint32_t*)&h2; u.w = *(uint32_t*)&h3;
        *(uint4*)&dst[i] = u;
        return;
    }

    __shared__ float t[32][33];
    const int r  = bid - 3072;
    const int b  = r >> 11;
    const int rr = r & 2047;
    const int l0 = (rr >> 5) * 32;
    const int d0 = (rr & 31) * 32;
    const int tx = tid & 31;
    const int ty = tid >> 5;
#pragma unroll
    for (int j = 0; j < 4; j++)
        t[ty + 8 * j][tx] = x[(size_t)b * Lc * Dc + (size_t)(l0 + ty + 8 * j) * Dc + d0 + tx];
    __syncthreads();
#pragma unroll
    for (int j = 0; j < 4; j++)
        xTh[(size_t)b * Dc * Lc + (size_t)(d0 + ty + 8 * j) * Lc + l0 + tx] =
            __float2half_rn(t[tx][ty + 8 * j]);
}

// ---------------------------------------------------------------------------
// K4': gs-fold + head-mean + decay + renormalize (unchanged from R14).
// ---------------------------------------------------------------------------
__global__ __launch_bounds__(256)
void attn_kernel(const __half* __restrict__ E, const float* __restrict__ part,
                 const float* __restrict__ td, float* __restrict__ attn,
                 __half* __restrict__ attnH, int store_f32)
{
    const int bq = blockIdx.x;
    const int b  = bq >> 11;
    const int q  = bq & (Lc - 1);
    const int tid = threadIdx.x;

    __shared__ float red2[256];
    __shared__ float ish[Hc];
    __shared__ float red[8];

    {
        const int h = tid >> 4, kt = tid & 15;
        red2[tid] = part[((size_t)((b * Hc + h) * 16 + kt)) * Lc + q];
    }
    __syncthreads();
    if (tid < Hc) {
        float s = 0.0f;
#pragma unroll
        for (int kt = 0; kt < 16; kt++) s += red2[tid * 16 + kt];
        ish[tid] = 1.0f / (16.0f * s);
    }
    __syncthreads();

    const __half* Eq = E + (size_t)bq * Hc * Lc;

    const float4 t0 = __ldcs((const float4*)&td[(size_t)bq * Lc + 8 * tid]);
    const float4 t1 = __ldcs((const float4*)&td[(size_t)bq * Lc + 8 * tid + 4]);

    float acc[8];
#pragma unroll
    for (int j = 0; j < 8; j++) acc[j] = 0.0f;

#pragma unroll
    for (int hb = 0; hb < Hc; hb += 4) {
        uint4 u[4];
#pragma unroll
        for (int i = 0; i < 4; i++)
            u[i] = __ldcs((const uint4*)&Eq[(size_t)(hb + i) * Lc + 8 * tid]);
#pragma unroll
        for (int i = 0; i < 4; i++) {
            const float is = ish[hb + i];
            float2 f0 = __half22float2(*(const __half2*)&u[i].x);
            float2 f1 = __half22float2(*(const __half2*)&u[i].y);
            float2 f2 = __half22float2(*(const __half2*)&u[i].z);
            float2 f3 = __half22float2(*(const __half2*)&u[i].w);
            acc[0] += f0.x * is; acc[1] += f0.y * is;
            acc[2] += f1.x * is; acc[3] += f1.y * is;
            acc[4] += f2.x * is; acc[5] += f2.y * is;
            acc[6] += f3.x * is; acc[7] += f3.y * is;
        }
    }

    float w[8];
    w[0] = acc[0] * __expf(-0.1f * t0.x);
    w[1] = acc[1] * __expf(-0.1f * t0.y);
    w[2] = acc[2] * __expf(-0.1f * t0.z);
    w[3] = acc[3] * __expf(-0.1f * t0.w);
    w[4] = acc[4] * __expf(-0.1f * t1.x);
    w[5] = acc[5] * __expf(-0.1f * t1.y);
    w[6] = acc[6] * __expf(-0.1f * t1.z);
    w[7] = acc[7] * __expf(-0.1f * t1.w);

    float lsum = 0.0f;
#pragma unroll
    for (int j = 0; j < 8; j++) lsum += w[j];
#pragma unroll
    for (int o = 16; o; o >>= 1) lsum += __shfl_xor_sync(0xFFFFFFFFu, lsum, o);
    if ((tid & 31) == 0) red[tid >> 5] = lsum;
    __syncthreads();
    if (tid == 0) {
        float t = 0.0f;
#pragma unroll
        for (int i = 0; i < 8; i++) t += red[i];
        red[0] = 1.0f / (t + 1e-8f);
    }
    __syncthreads();
    const float inv = red[0];

    float o[8];
#pragma unroll
    for (int j = 0; j < 8; j++) o[j] = w[j] * inv;
    if (store_f32) {
        __stcs((float4*)&attn[(size_t)bq * Lc + 8 * tid],
               make_float4(o[0], o[1], o[2], o[3]));
        __stcs((float4*)&attn[(size_t)bq * Lc + 8 * tid + 4],
               make_float4(o[4], o[5], o[6], o[7]));
    }

    __half2 h0 = __floats2half2_rn(o[0], o[1]);
    __half2 h1 = __floats2half2_rn(o[2], o[3]);
    __half2 h2 = __floats2half2_rn(o[4], o[5]);
    __half2 h3 = __floats2half2_rn(o[6], o[7]);
    uint4 u;
    u.x = *(uint32_t*)&h0; u.y = *(uint32_t*)&h1;
    u.z = *(uint32_t*)&h2; u.w = *(uint32_t*)&h3;
    *(uint4*)&attnH[(size_t)bq * Lc + 8 * tid] = u;
}

// ---------------------------------------------------------------------------
extern "C" void kernel_launch(void* const* d_in, const int* in_sizes, int n_in,
                              void* d_out, int out_size)
{
    const float* x    = (const float*)d_in[0];   // [B,L,D]
    const float* td   = (const float*)d_in[1];   // [B,L,L]
    const float* W    = (const float*)d_in[2];   // [3D,D]
    const float* bias = (const float*)d_in[3];   // [3D]
    float* out = (float*)d_out;

    __half *qk, *S, *xh, *Wh, *xTh, *atnH;
    float *part, *attn_scratch;
    cudaGetSymbolAddress((void**)&qk, g_qk);
    cudaGetSymbolAddress((void**)&S, g_S);
    cudaGetSymbolAddress((void**)&xh, g_xh);
    cudaGetSymbolAddress((void**)&Wh, g_Wh);
    cudaGetSymbolAddress((void**)&xTh, g_xTh);
    cudaGetSymbolAddress((void**)&atnH, g_atnH);
    cudaGetSymbolAddress((void**)&part, g_part);
    cudaGetSymbolAddress((void**)&attn_scratch, g_attn);

    cudaFuncSetAttribute(gemm_h<0, float>,  cudaFuncAttributeMaxDynamicSharedMemorySize, SMEM_GEMM_BYTES);
    cudaFuncSetAttribute(gemm_h<1, __half>, cudaFuncAttributeMaxDynamicSharedMemorySize, SMEM_GEMM_BYTES);
    cudaFuncSetAttribute(gemm_exp_kernel,   cudaFuncAttributeMaxDynamicSharedMemorySize, SMEM_K2_BYTES);

    const long outElems  = (long)Bc * Lc * Dc;   // 4,194,304
    const long attnElems = (long)Bc * Lc * Lc;   // 8,388,608
    const bool wantAttn = ((long)out_size >= outElems + attnElems);
    float* out_o = out;
    float* out_a = wantAttn ? (out + outElems) : attn_scratch;

    // P: fp16 copies of x, W[:2048] + fp16 x^T (single launch)
    prep_kernel<<<7168, 256>>>(x, W, xh, Wh, xTh);

    // K1: qk = fp16(xh @ Wh^T + bias)
    {
        dim3 grid(2 * Dc / 128, (Bc * Lc) / 128, 1);
        gemm_h<1, __half><<<grid, 256, SMEM_GEMM_BYTES>>>(
            xh, Dc, 0, 0,
            Wh, Dc, 0, 0,
            qk, 2 * Dc, 0, 0,
            1, Dc, 1.0f, bias);
    }

    // K2: S[b][q][h][k] = fp16(exp(0.125*Q@K^T - 6)) + per-tile row sums
    //     64x128 tiles, 4 CTA/SM
    {
        dim3 grid(Lc / 128, Lc / 64, Bc * Hc);   // (16, 32, 32)
        gemm_exp_kernel<<<grid, 256, SMEM_K2_BYTES>>>(qk, S, part);
    }

    // K4': gs-fold + head-mean + decay + renormalize -> attnH (+fp32 if wanted)
    attn_kernel<<<Bc * Lc, 256>>>(S, part, td, out_a, atnH, wantAttn ? 1 : 0);

    // K5: output = attnH @ xTh^T
    {
        dim3 grid(Dc / 128, Lc / 128, Bc);
        gemm_h<0, float><<<grid, 256, SMEM_GEMM_BYTES>>>(
            atnH, Lc, (long)Lc * Lc, 0,
            xTh,  Lc, (long)Dc * Lc, 0,
            out_o, Dc, (long)Lc * Dc, 0,
            1, Lc, 1.0f, nullptr);
    }
}

// round 16
// speedup vs baseline: 1.0720x; 1.0101x over previous
#include <cuda_runtime.h>
#include <cuda_fp16.h>
#include <cstdint>

// Problem constants
static constexpr int Bc  = 2;
static constexpr int Lc  = 2048;
static constexpr int Dc  = 1024;
static constexpr int Hc  = 16;

// Scratch (__device__ globals: allocation-free rule)
__device__ __half g_qk  [(size_t)Bc * Lc * 2 * Dc];     // [4096][2048] q|k fp16
__device__ __half g_S   [(size_t)Bc * Lc * Hc * Lc];    // exp(score-6) fp16, [b][q][h][k]
__device__ __half g_xh  [(size_t)Bc * Lc * Dc];         // x fp16
__device__ __half g_Wh  [(size_t)2 * Dc * Dc];          // W[:2048] fp16
__device__ __half g_xTh [(size_t)Bc * Dc * Lc];         // x^T fp16
__device__ __half g_atnH[(size_t)Bc * Lc * Lc];         // attn fp16 (K5 operand)
__device__ float  g_part[(size_t)Bc * Hc * 16 * Lc];    // per-ktile row sums
__device__ float  g_attn[(size_t)Bc * Lc * Lc];         // fallback attn buffer

// ---------------------------------------------------------------------------
__device__ __forceinline__ uint32_t smem_u32(const void* p) {
    uint32_t a;
    asm("{ .reg .u64 t; cvta.to.shared.u64 t, %1; cvt.u32.u64 %0, t; }" : "=r"(a) : "l"(p));
    return a;
}
__device__ __forceinline__ void mma16(float* c, const uint32_t* a, const uint32_t* b) {
    asm volatile(
        "mma.sync.aligned.m16n8k16.row.col.f32.f16.f16.f32 "
        "{%0,%1,%2,%3}, {%4,%5,%6,%7}, {%8,%9}, {%0,%1,%2,%3};"
        : "+f"(c[0]), "+f"(c[1]), "+f"(c[2]), "+f"(c[3])
        : "r"(a[0]), "r"(a[1]), "r"(a[2]), "r"(a[3]), "r"(b[0]), "r"(b[1]));
}
#define LDMX4(r0, r1, r2, r3, addr) \
    asm volatile("ldmatrix.sync.aligned.m8n8.x4.shared.b16 {%0,%1,%2,%3}, [%4];" \
        : "=r"(r0), "=r"(r1), "=r"(r2), "=r"(r3) : "r"(addr))
__device__ __forceinline__ void cp_async16(uint32_t dst, const void* src) {
    asm volatile("cp.async.cg.shared.global [%0], [%1], 16;" :: "r"(dst), "l"(src));
}
#define CP_COMMIT() asm volatile("cp.async.commit_group;" ::: "memory")
#define CP_WAIT(N)  asm volatile("cp.async.wait_group %0;" :: "n"(N) : "memory")

static constexpr int CHUNK = 64;
static constexpr int PADH  = 72;                        // 64 + 8 pad halves
static constexpr int AB_HALVES = 128 * PADH;            // 9216
static constexpr int STAGE_HALVES = 2 * AB_HALVES;      // A then B
static constexpr int NSTAGE = 3;
static constexpr int SMEM_GEMM_BYTES = NSTAGE * STAGE_HALVES * 2;   // 110592

// ---------------------------------------------------------------------------
// fp16 warp-MMA GEMM (K1/K5): C = f(alpha * A @ B^T)   [R12 best config]
// EPI: 0 = fp32 store (streaming), 1 = +bias -> fp16
// 256 thr = 8 warps (4m x 2n), warp tile 32x64, k-chunk 64, 3-stage ring.
// ---------------------------------------------------------------------------
template <int EPI, typename CT>
__global__ __launch_bounds__(256, 2)
void gemm_h(const __half* __restrict__ A, int lda, long aOut, long aIn,
            const __half* __restrict__ B, int ldb, long bOut, long bIn,
            CT* __restrict__ C, int ldc, long cOut, long cIn,
            int zInner, int Kd, float alpha, const float* __restrict__ bias)
{
    extern __shared__ __align__(16) char smemc[];
    const uint32_t sb = smem_u32(smemc);

    const int tid  = threadIdx.x;
    const int wid  = tid >> 5;
    const int lane = tid & 31;
    const int wm   = wid >> 1;
    const int wn   = wid & 1;
    const int lq   = lane >> 2;
    const int lr   = lane & 3;

    const int z  = blockIdx.z;
    const int zo = z / zInner, zi = z % zInner;
    A += (long)zo * aOut + (long)zi * aIn;
    B += (long)zo * bOut + (long)zi * bIn;
    C += (long)zo * cOut + (long)zi * cIn;

    const int m0 = blockIdx.y * 128;
    const int n0 = blockIdx.x * 128;

    float acc[2][8][4];
#pragma unroll
    for (int mt = 0; mt < 2; mt++)
#pragma unroll
        for (int nt = 0; nt < 8; nt++)
#pragma unroll
            for (int i = 0; i < 4; i++) acc[mt][nt][i] = 0.0f;

    const int nc = Kd / CHUNK;

    auto preload = [&](int c, int s) {
        const int k0 = c * CHUNK;
        const uint32_t abase = sb + (uint32_t)(s * STAGE_HALVES) * 2;
        const uint32_t bbase = abase + (uint32_t)AB_HALVES * 2;
#pragma unroll
        for (int j = 0; j < 4; j++) {
            const int f   = j * 256 + tid;
            const int row = f >> 3;
            const int c8  = f & 7;
            const uint32_t off = (uint32_t)(row * PADH + c8 * 8) * 2;
            cp_async16(abase + off, &A[(size_t)(m0 + row) * lda + k0 + c8 * 8]);
            cp_async16(bbase + off, &B[(size_t)(n0 + row) * ldb + k0 + c8 * 8]);
        }
    };

    preload(0, 0);
    CP_COMMIT();
    if (nc > 1) { preload(1, 1); CP_COMMIT(); }

    int s = 0;
    for (int c = 0; c < nc; c++) {
        if (c + 1 < nc) { CP_WAIT(1); } else { CP_WAIT(0); }
        __syncthreads();
        if (c + 2 < nc) {
            int s2 = s + 2; if (s2 >= NSTAGE) s2 -= NSTAGE;
            preload(c + 2, s2);
            CP_COMMIT();
        }

        const uint32_t stA = sb + (uint32_t)(s * STAGE_HALVES) * 2;
        const uint32_t stB = stA + (uint32_t)AB_HALVES * 2;

#pragma unroll
        for (int kh = 0; kh < CHUNK / 16; kh++) {
            uint32_t af[2][4];
#pragma unroll
            for (int mt = 0; mt < 2; mt++) {
                const int row = wm * 32 + mt * 16 + (lane & 7) + ((lane >> 3) & 1) * 8;
                const int col = kh * 16 + (lane >> 4) * 8;
                LDMX4(af[mt][0], af[mt][1], af[mt][2], af[mt][3],
                      stA + (uint32_t)(row * PADH + col) * 2);
            }
#pragma unroll
            for (int np = 0; np < 4; np++) {
                const int rowb = wn * 64 + np * 16 + (lane >> 4) * 8 + (lane & 7);
                const int colk = kh * 16 + ((lane >> 3) & 1) * 8;
                uint32_t bf[4];
                LDMX4(bf[0], bf[1], bf[2], bf[3],
                      stB + (uint32_t)(rowb * PADH + colk) * 2);
                mma16(acc[0][np * 2    ], af[0], bf + 0);
                mma16(acc[1][np * 2    ], af[1], bf + 0);
                mma16(acc[0][np * 2 + 1], af[0], bf + 2);
                mma16(acc[1][np * 2 + 1], af[1], bf + 2);
            }
        }
        if (++s >= NSTAGE) s -= NSTAGE;
    }
    __syncthreads();

    // ---- epilogue: regs -> fp32 staged smem -> coalesced GMEM ----
    float* stg = (float*)smemc;                        // 128 x 132 floats
#pragma unroll
    for (int mt = 0; mt < 2; mt++) {
        const int r = wm * 32 + mt * 16 + lq;
#pragma unroll
        for (int nt = 0; nt < 8; nt++) {
            const int cI = wn * 64 + nt * 8 + 2 * lr;
            *(float2*)&stg[(r    ) * 132 + cI] =
                make_float2(acc[mt][nt][0] * alpha, acc[mt][nt][1] * alpha);
            *(float2*)&stg[(r + 8) * 132 + cI] =
                make_float2(acc[mt][nt][2] * alpha, acc[mt][nt][3] * alpha);
        }
    }
    __syncthreads();

    float4 bv = make_float4(0.f, 0.f, 0.f, 0.f);
    if (EPI == 1) bv = *(const float4*)&bias[n0 + lane * 4];
#pragma unroll
    for (int it = 0; it < 16; it++) {
        const int r2 = it * 8 + wid;
        float4 v = *(const float4*)&stg[r2 * 132 + lane * 4];
        if (EPI == 1) { v.x += bv.x; v.y += bv.y; v.z += bv.z; v.w += bv.w; }
        if (EPI == 0) {
            __stcs((float4*)&C[(size_t)(m0 + r2) * ldc + n0 + lane * 4], v);
        } else {
            __half2 h0 = __floats2half2_rn(v.x, v.y);
            __half2 h1 = __floats2half2_rn(v.z, v.w);
            uint2 u;
            u.x = *(uint32_t*)&h0; u.y = *(uint32_t*)&h1;
            *(uint2*)&C[(size_t)(m0 + r2) * ldc + n0 + lane * 4] = u;
        }
    }
}

// ---------------------------------------------------------------------------
// K2: 64x128 tile, 256 thr = 8 warps (2m x 4n), warp tile 32x32, single K=64
// chunk, 4 CTA/SM. Row sums fused into exp phase (register accumulation +
// shfl + 1KB smem cross-warp fold) — no staging re-read pass.
// ---------------------------------------------------------------------------
static constexpr int PADS = 136;                          // staging halves/row
static constexpr int A64_HALVES = 64 * PADH;              // 4608
static constexpr int B64_HALVES = 128 * PADH;             // 9216
static constexpr int SMEM_K2_BYTES = (A64_HALVES + B64_HALVES) * 2;   // 27648
static constexpr int OFF_SUMS = 64 * PADS * 2;            // 17408 (16B aligned)
// sums: 64 rows x 4 wn floats = 1024 B -> 18432 <= 27648  OK

__global__ __launch_bounds__(256, 4)
void gemm_exp_kernel(const __half* __restrict__ qk, __half* __restrict__ S,
                     float* __restrict__ partial)
{
    extern __shared__ __align__(16) char smemc[];
    const uint32_t sb = smem_u32(smemc);

    const int tid  = threadIdx.x;
    const int wid  = tid >> 5;          // 0..7
    const int lane = tid & 31;
    const int wm   = wid >> 2;          // 0..1  (m: 64 rows)
    const int wn   = wid & 3;           // 0..3  (n: 128 cols)
    const int lq   = lane >> 2;         // 0..7
    const int lr   = lane & 3;          // 0..3

    const int z = blockIdx.z;           // b*16 + h
    const int b = z >> 4, h = z & 15;
    const int m0 = blockIdx.y * 64;     // q base (64-tile)
    const int n0 = blockIdx.x * 128;    // k base

    const __half* A = qk + (size_t)b * Lc * 2 * Dc + (size_t)h * 64;   // q
    const __half* B = A + Dc;                                          // k
    const int ld = 2 * Dc;

    const uint32_t abase = sb;
    const uint32_t bbase = sb + (uint32_t)A64_HALVES * 2;

    // load A (64x64) + B (128x64) tiles
    {
#pragma unroll
        for (int j = 0; j < 2; j++) {               // A: 512 float4 slots
            const int f   = j * 256 + tid;
            const int row = f >> 3;
            const int c8  = f & 7;
            cp_async16(abase + (uint32_t)(row * PADH + c8 * 8) * 2,
                       &A[(size_t)(m0 + row) * ld + c8 * 8]);
        }
#pragma unroll
        for (int j = 0; j < 4; j++) {               // B: 1024 float4 slots
            const int f   = j * 256 + tid;
            const int row = f >> 3;
            const int c8  = f & 7;
            cp_async16(bbase + (uint32_t)(row * PADH + c8 * 8) * 2,
                       &B[(size_t)(n0 + row) * ld + c8 * 8]);
        }
    }
    CP_COMMIT();
    CP_WAIT(0);
    __syncthreads();

    float acc[2][4][4];
#pragma unroll
    for (int mt = 0; mt < 2; mt++)
#pragma unroll
        for (int nt = 0; nt < 4; nt++)
#pragma unroll
            for (int i = 0; i < 4; i++) acc[mt][nt][i] = 0.0f;

#pragma unroll
    for (int kh = 0; kh < 4; kh++) {
        uint32_t af[2][4];
#pragma unroll
        for (int mt = 0; mt < 2; mt++) {
            const int row = wm * 32 + mt * 16 + (lane & 7) + ((lane >> 3) & 1) * 8;
            const int col = kh * 16 + (lane >> 4) * 8;
            LDMX4(af[mt][0], af[mt][1], af[mt][2], af[mt][3],
                  abase + (uint32_t)(row * PADH + col) * 2);
        }
#pragma unroll
        for (int np = 0; np < 2; np++) {
            const int rowb = wn * 32 + np * 16 + (lane >> 4) * 8 + (lane & 7);
            const int colk = kh * 16 + ((lane >> 3) & 1) * 8;
            uint32_t bf[4];
            LDMX4(bf[0], bf[1], bf[2], bf[3],
                  bbase + (uint32_t)(rowb * PADH + colk) * 2);
            mma16(acc[0][np * 2    ], af[0], bf + 0);
            mma16(acc[1][np * 2    ], af[1], bf + 0);
            mma16(acc[0][np * 2 + 1], af[0], bf + 2);
            mma16(acc[1][np * 2 + 1], af[1], bf + 2);
        }
    }
    __syncthreads();            // operand smem about to be reused as staging

    // exp + fp16 staging + fused row-sum accumulation
    __half* stgh = (__half*)smemc;                  // 64 x PADS halves
    float*  sums = (float*)(smemc + OFF_SUMS);      // [64 rows][4 wn]
    float rs[2][2] = {{0.f, 0.f}, {0.f, 0.f}};      // [mt][half]
#pragma unroll
    for (int mt = 0; mt < 2; mt++) {
        const int r = wm * 32 + mt * 16 + lq;
#pragma unroll
        for (int nt = 0; nt < 4; nt++) {
            const int cI = wn * 32 + nt * 8 + 2 * lr;
            float v0 = __expf(0.125f * acc[mt][nt][0] - 6.0f);
            float v1 = __expf(0.125f * acc[mt][nt][1] - 6.0f);
            float v2 = __expf(0.125f * acc[mt][nt][2] - 6.0f);
            float v3 = __expf(0.125f * acc[mt][nt][3] - 6.0f);
            *(__half2*)&stgh[(r    ) * PADS + cI] = __floats2half2_rn(v0, v1);
            *(__half2*)&stgh[(r + 8) * PADS + cI] = __floats2half2_rn(v2, v3);
            rs[mt][0] += v0 + v1;
            rs[mt][1] += v2 + v3;
        }
    }
    // reduce over the 4 lanes (lr) sharing each row
#pragma unroll
    for (int mt = 0; mt < 2; mt++)
#pragma unroll
        for (int hf = 0; hf < 2; hf++) {
            rs[mt][hf] += __shfl_xor_sync(0xFFFFFFFFu, rs[mt][hf], 1);
            rs[mt][hf] += __shfl_xor_sync(0xFFFFFFFFu, rs[mt][hf], 2);
        }
    if (lr == 0) {
#pragma unroll
        for (int mt = 0; mt < 2; mt++) {
            const int r = wm * 32 + mt * 16 + lq;
            sums[(r    ) * 4 + wn] = rs[mt][0];
            sums[(r + 8) * 4 + wn] = rs[mt][1];
        }
    }
    __syncthreads();

    // fold 4 n-warps per row -> partial
    if (tid < 64) {
        const float p = sums[tid * 4 + 0] + sums[tid * 4 + 1] +
                        sums[tid * 4 + 2] + sums[tid * 4 + 3];
        partial[(size_t)(z * 16 + blockIdx.x) * Lc + m0 + tid] = p;
    }

    // store S (streaming): [b][q][h][k]; 64x128 halves = 1024 uint4 slots
#pragma unroll
    for (int it = 0; it < 4; it++) {
        const int slot = tid + it * 256;
        const int row  = slot >> 4;
        const int c16  = slot & 15;
        const uint4 u = *(const uint4*)&stgh[row * PADS + c16 * 8];
        __stcs((uint4*)&S[(((size_t)b * Lc + m0 + row) * Hc + h) * Lc + n0 + c16 * 8], u);
    }
}

// ---------------------------------------------------------------------------
// Combined prep kernel (one launch)
// ---------------------------------------------------------------------------
__global__ __launch_bounds__(256)
void prep_kernel(const float* __restrict__ x, const float* __restrict__ W,
                 __half* __restrict__ xh, __half* __restrict__ Wh,
                 __half* __restrict__ xTh)
{
    const int bid = blockIdx.x;
    const int tid = threadIdx.x;

    if (bid < 3072) {
        const float* src = (bid < 2048) ? x : W;
        __half* dst      = (bid < 2048) ? xh : Wh;
        const size_t base = (size_t)(bid < 2048 ? bid : bid - 2048) * 2048;
        const size_t i = base + (size_t)tid * 8;
        float4 a = *(const float4*)&src[i];
        float4 b = *(const float4*)&src[i + 4];
        __half2 h0 = __floats2half2_rn(a.x, a.y);
        __half2 h1 = __floats2half2_rn(a.z, a.w);
        __half2 h2 = __floats2half2_rn(b.x, b.y);
        __half2 h3 = __floats2half2_rn(b.z, b.w);
        uint4 u;
        u.x = *(uint32_t*)&h0; u.y = *(uint32_t*)&h1;
        u.z = *(uint32_t*)&h2; u.w = *(uint32_t*)&h3;
        *(uint4*)&dst[i] = u;
        return;
    }

    __shared__ float t[32][33];
    const int r  = bid - 3072;
    const int b  = r >> 11;
    const int rr = r & 2047;
    const int l0 = (rr >> 5) * 32;
    const int d0 = (rr & 31) * 32;
    const int tx = tid & 31;
    const int ty = tid >> 5;
#pragma unroll
    for (int j = 0; j < 4; j++)
        t[ty + 8 * j][tx] = x[(size_t)b * Lc * Dc + (size_t)(l0 + ty + 8 * j) * Dc + d0 + tx];
    __syncthreads();
#pragma unroll
    for (int j = 0; j < 4; j++)
        xTh[(size_t)b * Dc * Lc + (size_t)(d0 + ty + 8 * j) * Lc + l0 + tx] =
            __float2half_rn(t[tx][ty + 8 * j]);
}

// ---------------------------------------------------------------------------
// K4': gs-fold + head-mean + decay + renormalize. 8-wide head batching (MLP).
// ---------------------------------------------------------------------------
__global__ __launch_bounds__(256)
void attn_kernel(const __half* __restrict__ E, const float* __restrict__ part,
                 const float* __restrict__ td, float* __restrict__ attn,
                 __half* __restrict__ attnH, int store_f32)
{
    const int bq = blockIdx.x;
    const int b  = bq >> 11;
    const int q  = bq & (Lc - 1);
    const int tid = threadIdx.x;

    __shared__ float red2[256];
    __shared__ float ish[Hc];
    __shared__ float red[8];

    {
        const int h = tid >> 4, kt = tid & 15;
        red2[tid] = part[((size_t)((b * Hc + h) * 16 + kt)) * Lc + q];
    }
    __syncthreads();
    if (tid < Hc) {
        float s = 0.0f;
#pragma unroll
        for (int kt = 0; kt < 16; kt++) s += red2[tid * 16 + kt];
        ish[tid] = 1.0f / (16.0f * s);
    }
    __syncthreads();

    const __half* Eq = E + (size_t)bq * Hc * Lc;

    const float4 t0 = __ldcs((const float4*)&td[(size_t)bq * Lc + 8 * tid]);
    const float4 t1 = __ldcs((const float4*)&td[(size_t)bq * Lc + 8 * tid + 4]);

    float acc[8];
#pragma unroll
    for (int j = 0; j < 8; j++) acc[j] = 0.0f;

#pragma unroll
    for (int hb = 0; hb < Hc; hb += 8) {
        uint4 u[8];
#pragma unroll
        for (int i = 0; i < 8; i++)
            u[i] = __ldcs((const uint4*)&Eq[(size_t)(hb + i) * Lc + 8 * tid]);
#pragma unroll
        for (int i = 0; i < 8; i++) {
            const float is = ish[hb + i];
            float2 f0 = __half22float2(*(const __half2*)&u[i].x);
            float2 f1 = __half22float2(*(const __half2*)&u[i].y);
            float2 f2 = __half22float2(*(const __half2*)&u[i].z);
            float2 f3 = __half22float2(*(const __half2*)&u[i].w);
            acc[0] += f0.x * is; acc[1] += f0.y * is;
            acc[2] += f1.x * is; acc[3] += f1.y * is;
            acc[4] += f2.x * is; acc[5] += f2.y * is;
            acc[6] += f3.x * is; acc[7] += f3.y * is;
        }
    }

    float w[8];
    w[0] = acc[0] * __expf(-0.1f * t0.x);
    w[1] = acc[1] * __expf(-0.1f * t0.y);
    w[2] = acc[2] * __expf(-0.1f * t0.z);
    w[3] = acc[3] * __expf(-0.1f * t0.w);
    w[4] = acc[4] * __expf(-0.1f * t1.x);
    w[5] = acc[5] * __expf(-0.1f * t1.y);
    w[6] = acc[6] * __expf(-0.1f * t1.z);
    w[7] = acc[7] * __expf(-0.1f * t1.w);

    float lsum = 0.0f;
#pragma unroll
    for (int j = 0; j < 8; j++) lsum += w[j];
#pragma unroll
    for (int o = 16; o; o >>= 1) lsum += __shfl_xor_sync(0xFFFFFFFFu, lsum, o);
    if ((tid & 31) == 0) red[tid >> 5] = lsum;
    __syncthreads();
    if (tid == 0) {
        float t = 0.0f;
#pragma unroll
        for (int i = 0; i < 8; i++) t += red[i];
        red[0] = 1.0f / (t + 1e-8f);
    }
    __syncthreads();
    const float inv = red[0];

    float o[8];
#pragma unroll
    for (int j = 0; j < 8; j++) o[j] = w[j] * inv;
    if (store_f32) {
        __stcs((float4*)&attn[(size_t)bq * Lc + 8 * tid],
               make_float4(o[0], o[1], o[2], o[3]));
        __stcs((float4*)&attn[(size_t)bq * Lc + 8 * tid + 4],
               make_float4(o[4], o[5], o[6], o[7]));
    }

    __half2 h0 = __floats2half2_rn(o[0], o[1]);
    __half2 h1 = __floats2half2_rn(o[2], o[3]);
    __half2 h2 = __floats2half2_rn(o[4], o[5]);
    __half2 h3 = __floats2half2_rn(o[6], o[7]);
    uint4 u;
    u.x = *(uint32_t*)&h0; u.y = *(uint32_t*)&h1;
    u.z = *(uint32_t*)&h2; u.w = *(uint32_t*)&h3;
    *(uint4*)&attnH[(size_t)bq * Lc + 8 * tid] = u;
}

// ---------------------------------------------------------------------------
extern "C" void kernel_launch(void* const* d_in, const int* in_sizes, int n_in,
                              void* d_out, int out_size)
{
    const float* x    = (const float*)d_in[0];   // [B,L,D]
    const float* td   = (const float*)d_in[1];   // [B,L,L]
    const float* W    = (const float*)d_in[2];   // [3D,D]
    const float* bias = (const float*)d_in[3];   // [3D]
    float* out = (float*)d_out;

    __half *qk, *S, *xh, *Wh, *xTh, *atnH;
    float *part, *attn_scratch;
    cudaGetSymbolAddress((void**)&qk, g_qk);
    cudaGetSymbolAddress((void**)&S, g_S);
    cudaGetSymbolAddress((void**)&xh, g_xh);
    cudaGetSymbolAddress((void**)&Wh, g_Wh);
    cudaGetSymbolAddress((void**)&xTh, g_xTh);
    cudaGetSymbolAddress((void**)&atnH, g_atnH);
    cudaGetSymbolAddress((void**)&part, g_part);
    cudaGetSymbolAddress((void**)&attn_scratch, g_attn);

    cudaFuncSetAttribute(gemm_h<0, float>,  cudaFuncAttributeMaxDynamicSharedMemorySize, SMEM_GEMM_BYTES);
    cudaFuncSetAttribute(gemm_h<1, __half>, cudaFuncAttributeMaxDynamicSharedMemorySize, SMEM_GEMM_BYTES);
    cudaFuncSetAttribute(gemm_exp_kernel,   cudaFuncAttributeMaxDynamicSharedMemorySize, SMEM_K2_BYTES);

    const long outElems  = (long)Bc * Lc * Dc;   // 4,194,304
    const long attnElems = (long)Bc * Lc * Lc;   // 8,388,608
    const bool wantAttn = ((long)out_size >= outElems + attnElems);
    float* out_o = out;
    float* out_a = wantAttn ? (out + outElems) : attn_scratch;

    // P: fp16 copies of x, W[:2048] + fp16 x^T (single launch)
    prep_kernel<<<7168, 256>>>(x, W, xh, Wh, xTh);

    // K1: qk = fp16(xh @ Wh^T + bias)
    {
        dim3 grid(2 * Dc / 128, (Bc * Lc) / 128, 1);
        gemm_h<1, __half><<<grid, 256, SMEM_GEMM_BYTES>>>(
            xh, Dc, 0, 0,
            Wh, Dc, 0, 0,
            qk, 2 * Dc, 0, 0,
            1, Dc, 1.0f, bias);
    }

    // K2: S[b][q][h][k] = fp16(exp(0.125*Q@K^T - 6)) + fused row sums
    //     64x128 tiles, 4 CTA/SM
    {
        dim3 grid(Lc / 128, Lc / 64, Bc * Hc);   // (16, 32, 32)
        gemm_exp_kernel<<<grid, 256, SMEM_K2_BYTES>>>(qk, S, part);
    }

    // K4': gs-fold + head-mean + decay + renormalize -> attnH (+fp32 if wanted)
    attn_kernel<<<Bc * Lc, 256>>>(S, part, td, out_a, atnH, wantAttn ? 1 : 0);

    // K5: output = attnH @ xTh^T
    {
        dim3 grid(Dc / 128, Lc / 128, Bc);
        gemm_h<0, float><<<grid, 256, SMEM_GEMM_BYTES>>>(
            atnH, Lc, (long)Lc * Lc, 0,
            xTh,  Lc, (long)Dc * Lc, 0,
            out_o, Dc, (long)Lc * Dc, 0,
            1, Lc, 1.0f, nullptr);
    }
}